// round 8
// baseline (speedup 1.0000x reference)
#include <cuda_runtime.h>
#include <cuda_bf16.h>

#define NN 100000
#define EE 1600000
#define GG 2000
#define HH 128
#define LL 3
#define SCAN_B 512
#define SCAN_NB ((NN + SCAN_B - 1) / SCAN_B)   // 196
#define PITCH 132        // 4*PITCH % 32 == 16 -> rows 4 apart hit different banks
#define NTILES ((NN + 63) / 64)                // 1563
#define NCTA 296

// named-barrier ids: FULL buf0/1 = 1/2, EMPTY buf0/1 = 3/4, consumer-internal = 5
#define BAR_SYNC(id, cnt)   asm volatile("bar.sync %0, %1;"   :: "r"(id), "r"(cnt) : "memory")
#define BAR_ARRIVE(id, cnt) asm volatile("bar.arrive %0, %1;" :: "r"(id), "r"(cnt) : "memory")

// Scratch (__device__ globals; no allocations allowed)
__device__ float g_h [NN * HH];
__device__ float g_h2[NN * HH];
__device__ int   g_off[NN + 1];
__device__ int   g_cur[NN];
__device__ int   g_csr[EE];
__device__ int   g_bsum[256];
__device__ int   g_bpre[256];
__device__ float g_gsum[GG * HH];
__device__ int   g_gcnt[GG];

// ---------------------------------------------------------------------------
__global__ void proj_kernel(const float* __restrict__ x,
                            const float* __restrict__ pw,
                            const float* __restrict__ pb,
                            float* __restrict__ h) {
    int n = blockIdx.x;
    int j = threadIdx.x;
    const float* xr = x + (size_t)n * 4;
    float acc = pb[j];
    acc += xr[0] * pw[0 * HH + j];
    acc += xr[1] * pw[1 * HH + j];
    acc += xr[2] * pw[2 * HH + j];
    acc += xr[3] * pw[3 * HH + j];
    h[(size_t)n * HH + j] = acc;
}

// ---------------------------------------------------------------------------
__global__ void zero_kernel(int* __restrict__ deg,
                            float* __restrict__ gsum, int* __restrict__ gcnt) {
    int i = blockIdx.x * blockDim.x + threadIdx.x;
    if (i <= NN) deg[i] = 0;
    if (i < GG * HH) gsum[i] = 0.f;
    if (i < GG) gcnt[i] = 0;
}

__global__ void hist_kernel(const int* __restrict__ ei, int* __restrict__ deg) {
    int e = blockIdx.x * blockDim.x + threadIdx.x;
    if (e < EE) atomicAdd(deg + __ldg(ei + EE + e), 1);
}

__global__ void scan1_kernel(int* __restrict__ off, int* __restrict__ bsum) {
    __shared__ int s[SCAN_B];
    int t = threadIdx.x;
    int i = blockIdx.x * SCAN_B + t;
    int v = (i < NN) ? off[i] : 0;
    s[t] = v;
    __syncthreads();
    for (int o = 1; o < SCAN_B; o <<= 1) {
        int x = (t >= o) ? s[t - o] : 0;
        __syncthreads();
        s[t] += x;
        __syncthreads();
    }
    if (i < NN) off[i] = s[t] - v;
    if (t == SCAN_B - 1) bsum[blockIdx.x] = s[t];
}

__global__ void scan2_kernel(const int* __restrict__ bsum, int* __restrict__ bpre) {
    __shared__ int s[256];
    int t = threadIdx.x;
    int v = (t < SCAN_NB) ? bsum[t] : 0;
    s[t] = v;
    __syncthreads();
    for (int o = 1; o < 256; o <<= 1) {
        int x = (t >= o) ? s[t - o] : 0;
        __syncthreads();
        s[t] += x;
        __syncthreads();
    }
    if (t < SCAN_NB) bpre[t] = s[t] - v;
}

__global__ void scan3_kernel(int* __restrict__ off, const int* __restrict__ bpre,
                             int* __restrict__ cur) {
    int i = blockIdx.x * blockDim.x + threadIdx.x;
    if (i < NN) {
        int o = off[i] + bpre[i / SCAN_B];
        off[i] = o;
        cur[i] = o;
    }
    if (i == NN) off[NN] = EE;
}

__global__ void fill_kernel(const int* __restrict__ ei,
                            int* __restrict__ cur, int* __restrict__ csr) {
    int e = blockIdx.x * blockDim.x + threadIdx.x;
    if (e < EE) {
        int s = __ldg(ei + e);
        int d = __ldg(ei + EE + e);
        int p = atomicAdd(cur + d, 1);
        csr[p] = s;
    }
}

// ---------------------------------------------------------------------------
// Warp-specialized fused layer kernel (persistent, strided tiles):
//   producers (warps 8-11, 128 thr): CSR gather of tile t+1 into buf[(t+1)%2]
//   consumers (warps 0-7, 256 thr):  MLP GEMMs on buf[t%2], write h_out
// Double-buffered pipeline via named barriers.
// dyn smem: sW (16*HH) + 2 tiles of 64*PITCH floats = 75776 B.
__global__ void __launch_bounds__(384, 2) mlp_ws_kernel(
    const float* __restrict__ in, float* __restrict__ out,
    const int* __restrict__ off, const int* __restrict__ csr,
    const float* __restrict__ W1, const float* __restrict__ B1,
    const float* __restrict__ W2, const float* __restrict__ B2) {
    extern __shared__ float smem[];
    float* sW  = smem;               // 16*HH floats
    float* sMT = smem + 16 * HH;     // 2 * 64*PITCH floats

    const int tid = threadIdx.x;

    if (tid >= 256) {
        // ---------------- producer: 4 warps, 16 rows each ----------------
        const int ptid = tid - 256;
        const int pw   = ptid >> 5;       // 0..3
        const int lane = ptid & 31;
        const float4* in4 = (const float4*)in;
        int i = 0;
        for (int tt = blockIdx.x; tt < NTILES; tt += NCTA, i++) {
            const int bi = i & 1;
            if (i >= 2) BAR_SYNC(3 + bi, 384);        // wait buffer empty
            float* buf = sMT + bi * (64 * PITCH);
            const int row0 = tt * 64;
#pragma unroll
            for (int jj = 0; jj < 8; jj++) {
                int r0 = pw * 16 + jj * 2;
                int n0 = row0 + r0;
                int n1 = n0 + 1;
                float4 a0 = make_float4(0.f, 0.f, 0.f, 0.f);
                float4 a1 = make_float4(0.f, 0.f, 0.f, 0.f);
                int d0 = 0, d1 = 0, s0 = 0, s1 = 0;
                if (n0 < NN) {
                    a0 = __ldg(in4 + (size_t)n0 * 32 + lane);
                    s0 = __ldg(off + n0);
                    d0 = __ldg(off + n0 + 1) - s0;
                }
                if (n1 < NN) {
                    a1 = __ldg(in4 + (size_t)n1 * 32 + lane);
                    s1 = __ldg(off + n1);
                    d1 = __ldg(off + n1 + 1) - s1;
                }
                int dmax = d0 > d1 ? d0 : d1;
#pragma unroll 4
                for (int e = 0; e < dmax; e++) {
                    if (e < d0) {                       // warp-uniform
                        int s = __ldg(csr + s0 + e);
                        float4 v = __ldg(in4 + (size_t)s * 32 + lane);
                        a0.x += v.x; a0.y += v.y; a0.z += v.z; a0.w += v.w;
                    }
                    if (e < d1) {                       // warp-uniform
                        int s = __ldg(csr + s1 + e);
                        float4 v = __ldg(in4 + (size_t)s * 32 + lane);
                        a1.x += v.x; a1.y += v.y; a1.z += v.z; a1.w += v.w;
                    }
                }
                *(float4*)(buf + r0 * PITCH + lane * 4)       = a0;
                *(float4*)(buf + (r0 + 1) * PITCH + lane * 4) = a1;
            }
            __threadfence_block();
            BAR_ARRIVE(1 + bi, 384);                   // signal buffer full
        }
    } else {
        // ---------------- consumer: 8 warps, 64x128 double-GEMM ----------------
        const int rb = tid >> 4;            // 0..15 -> rows rb*4+i
        const int cg = (tid & 15) * 8;      // 0..120 step 8
        int i = 0;
        for (int tt = blockIdx.x; tt < NTILES; tt += NCTA, i++) {
            const int bi = i & 1;
            BAR_SYNC(1 + bi, 384);                     // wait buffer full
            float* buf = sMT + bi * (64 * PITCH);
            const int row0 = tt * 64;

            float acc[4][8];
#pragma unroll
            for (int a = 0; a < 4; a++)
#pragma unroll
                for (int b = 0; b < 8; b++) acc[a][b] = 0.f;

            // ---- GEMM 1: t = m @ W1 ----
            for (int kc = 0; kc < HH; kc += 16) {
                BAR_SYNC(5, 256);
                for (int q = tid; q < 16 * 32; q += 256)
                    ((float4*)sW)[q] = ((const float4*)(W1 + (size_t)kc * HH))[q];
                BAR_SYNC(5, 256);
#pragma unroll
                for (int k = 0; k < 16; k++) {
                    float4 w0 = *(const float4*)(sW + k * HH + cg);
                    float4 w1 = *(const float4*)(sW + k * HH + cg + 4);
#pragma unroll
                    for (int a = 0; a < 4; a++) {
                        float m = buf[(rb * 4 + a) * PITCH + kc + k];
                        acc[a][0] += m * w0.x; acc[a][1] += m * w0.y;
                        acc[a][2] += m * w0.z; acc[a][3] += m * w0.w;
                        acc[a][4] += m * w1.x; acc[a][5] += m * w1.y;
                        acc[a][6] += m * w1.z; acc[a][7] += m * w1.w;
                    }
                }
            }
            BAR_SYNC(5, 256);   // all m reads done before overwrite

            // t = relu(acc + b1) -> buf
            {
                float4 b0 = *(const float4*)(B1 + cg);
                float4 b1 = *(const float4*)(B1 + cg + 4);
#pragma unroll
                for (int a = 0; a < 4; a++) {
                    int r = rb * 4 + a;
                    float4 t0, t1;
                    t0.x = fmaxf(acc[a][0] + b0.x, 0.f);
                    t0.y = fmaxf(acc[a][1] + b0.y, 0.f);
                    t0.z = fmaxf(acc[a][2] + b0.z, 0.f);
                    t0.w = fmaxf(acc[a][3] + b0.w, 0.f);
                    t1.x = fmaxf(acc[a][4] + b1.x, 0.f);
                    t1.y = fmaxf(acc[a][5] + b1.y, 0.f);
                    t1.z = fmaxf(acc[a][6] + b1.z, 0.f);
                    t1.w = fmaxf(acc[a][7] + b1.w, 0.f);
                    *(float4*)(buf + r * PITCH + cg)     = t0;
                    *(float4*)(buf + r * PITCH + cg + 4) = t1;
#pragma unroll
                    for (int b = 0; b < 8; b++) acc[a][b] = 0.f;
                }
            }

            // ---- GEMM 2: o = t @ W2 ----
            for (int kc = 0; kc < HH; kc += 16) {
                BAR_SYNC(5, 256);
                for (int q = tid; q < 16 * 32; q += 256)
                    ((float4*)sW)[q] = ((const float4*)(W2 + (size_t)kc * HH))[q];
                BAR_SYNC(5, 256);
#pragma unroll
                for (int k = 0; k < 16; k++) {
                    float4 w0 = *(const float4*)(sW + k * HH + cg);
                    float4 w1 = *(const float4*)(sW + k * HH + cg + 4);
#pragma unroll
                    for (int a = 0; a < 4; a++) {
                        float t = buf[(rb * 4 + a) * PITCH + kc + k];
                        acc[a][0] += t * w0.x; acc[a][1] += t * w0.y;
                        acc[a][2] += t * w0.z; acc[a][3] += t * w0.w;
                        acc[a][4] += t * w1.x; acc[a][5] += t * w1.y;
                        acc[a][6] += t * w1.z; acc[a][7] += t * w1.w;
                    }
                }
            }

            // h_out = relu(acc + b2)
            {
                float4 b0 = *(const float4*)(B2 + cg);
                float4 b1 = *(const float4*)(B2 + cg + 4);
#pragma unroll
                for (int a = 0; a < 4; a++) {
                    int n = row0 + rb * 4 + a;
                    if (n < NN) {
                        float4 o0, o1;
                        o0.x = fmaxf(acc[a][0] + b0.x, 0.f);
                        o0.y = fmaxf(acc[a][1] + b0.y, 0.f);
                        o0.z = fmaxf(acc[a][2] + b0.z, 0.f);
                        o0.w = fmaxf(acc[a][3] + b0.w, 0.f);
                        o1.x = fmaxf(acc[a][4] + b1.x, 0.f);
                        o1.y = fmaxf(acc[a][5] + b1.y, 0.f);
                        o1.z = fmaxf(acc[a][6] + b1.z, 0.f);
                        o1.w = fmaxf(acc[a][7] + b1.w, 0.f);
                        *(float4*)(out + (size_t)n * HH + cg)     = o0;
                        *(float4*)(out + (size_t)n * HH + cg + 4) = o1;
                    }
                }
            }
            BAR_ARRIVE(3 + bi, 384);                   // signal buffer empty
        }
    }
}

// ---------------------------------------------------------------------------
__global__ void pool_kernel(const float* __restrict__ h, const int* __restrict__ batch,
                            float* __restrict__ gsum, int* __restrict__ gcnt) {
    int n = (blockIdx.x * blockDim.x + threadIdx.x) >> 5;
    if (n >= NN) return;
    int lane = threadIdx.x & 31;
    int b = __ldg(batch + n);
    float4 v = ((const float4*)(h + (size_t)n * HH))[lane];
    float* dst = gsum + (size_t)b * HH + lane * 4;
    atomicAdd(dst + 0, v.x);
    atomicAdd(dst + 1, v.y);
    atomicAdd(dst + 2, v.z);
    atomicAdd(dst + 3, v.w);
    if (lane == 0) atomicAdd(gcnt + b, 1);
}

// ---------------------------------------------------------------------------
__global__ void head_kernel(const float* __restrict__ gsum, const int* __restrict__ gcnt,
                            const float* __restrict__ Ws, const float* __restrict__ Bs,
                            const float* __restrict__ ew, const float* __restrict__ eb,
                            const float* __restrict__ dw, const float* __restrict__ db,
                            float* __restrict__ out) {
    int g = blockIdx.x;
    int j = threadIdx.x;
    __shared__ float sg[HH];
    __shared__ float re[HH];
    __shared__ float rd[HH];

    float cnt = fmaxf((float)gcnt[g], 1.f);
    sg[j] = gsum[(size_t)g * HH + j] / cnt;
    __syncthreads();

    float a = Bs[j];
#pragma unroll 8
    for (int k = 0; k < HH; k++) a += sg[k] * Ws[k * HH + j];
    a = fmaxf(a, 0.f);

    re[j] = a * ew[j];
    rd[j] = a * dw[j];
    __syncthreads();
    for (int s = 64; s > 0; s >>= 1) {
        if (j < s) { re[j] += re[j + s]; rd[j] += rd[j + s]; }
        __syncthreads();
    }
    if (j == 0) {
        out[g]      = re[0] + eb[0];
        out[GG + g] = rd[0] + db[0];
    }
}

// ---------------------------------------------------------------------------
extern "C" void kernel_launch(void* const* d_in, const int* in_sizes, int n_in,
                              void* d_out, int out_size) {
    const float* x       = (const float*)d_in[0];
    const int*   ei      = (const int*)  d_in[1];
    const int*   batch   = (const int*)  d_in[2];
    const float* proj_w  = (const float*)d_in[3];
    const float* proj_b  = (const float*)d_in[4];
    const float* conv_w1 = (const float*)d_in[5];
    const float* conv_b1 = (const float*)d_in[6];
    const float* conv_w2 = (const float*)d_in[7];
    const float* conv_b2 = (const float*)d_in[8];
    const float* sh_w    = (const float*)d_in[9];
    const float* sh_b    = (const float*)d_in[10];
    const float* e_w     = (const float*)d_in[11];
    const float* e_b     = (const float*)d_in[12];
    const float* d_w     = (const float*)d_in[13];
    const float* d_b     = (const float*)d_in[14];
    float* out = (float*)d_out;

    float *h, *h2, *gsum;
    int *off, *cur, *csr, *bsum, *bpre, *gcnt;
    cudaGetSymbolAddress((void**)&h,    g_h);
    cudaGetSymbolAddress((void**)&h2,   g_h2);
    cudaGetSymbolAddress((void**)&off,  g_off);
    cudaGetSymbolAddress((void**)&cur,  g_cur);
    cudaGetSymbolAddress((void**)&csr,  g_csr);
    cudaGetSymbolAddress((void**)&bsum, g_bsum);
    cudaGetSymbolAddress((void**)&bpre, g_bpre);
    cudaGetSymbolAddress((void**)&gsum, g_gsum);
    cudaGetSymbolAddress((void**)&gcnt, g_gcnt);

    static int smem_set = 0;
    const int DYN_SMEM = (16 * HH + 2 * 64 * PITCH) * (int)sizeof(float);  // 75776
    if (!smem_set) {
        cudaFuncSetAttribute(mlp_ws_kernel,
                             cudaFuncAttributeMaxDynamicSharedMemorySize, DYN_SMEM);
        smem_set = 1;
    }

    // input projection
    proj_kernel<<<NN, HH>>>(x, proj_w, proj_b, h);

    // CSR build (edges grouped by destination); deg accumulates in off[]
    zero_kernel<<<(GG * HH + 255) / 256, 256>>>(off, gsum, gcnt);
    hist_kernel<<<(EE + 255) / 256, 256>>>(ei, off);
    scan1_kernel<<<SCAN_NB, SCAN_B>>>(off, bsum);
    scan2_kernel<<<1, 256>>>(bsum, bpre);
    scan3_kernel<<<(NN + 256) / 256, 256>>>(off, bpre, cur);
    fill_kernel<<<(EE + 255) / 256, 256>>>(ei, cur, csr);

    // GIN layers (warp-specialized fused gather+MLP; ping-pong h <-> h2)
    const float* src = h;
    float* dst = h2;
    for (int l = 0; l < LL; l++) {
        mlp_ws_kernel<<<NCTA, 384, DYN_SMEM>>>(src, dst, off, csr,
                                               conv_w1 + (size_t)l * HH * HH,
                                               conv_b1 + (size_t)l * HH,
                                               conv_w2 + (size_t)l * HH * HH,
                                               conv_b2 + (size_t)l * HH);
        const float* t = dst; dst = (float*)src; src = t;
    }
    const float* hf = src;   // final features

    pool_kernel<<<(NN * 32 + 255) / 256, 256>>>(hf, batch, gsum, gcnt);
    head_kernel<<<GG, HH>>>(gsum, gcnt, sh_w, sh_b, e_w, e_b, d_w, d_b, out);
}

// round 9
// speedup vs baseline: 1.0073x; 1.0073x over previous
#include <cuda_runtime.h>
#include <cuda_bf16.h>

#define NN 100000
#define EE 1600000
#define GG 2000
#define HH 128
#define LL 3
#define SCAN_B 512
#define SCAN_NB ((NN + SCAN_B - 1) / SCAN_B)   // 196
#define PITCH 132        // 4*PITCH % 32 == 16 -> rows 4 apart hit different banks
#define NTILES ((NN + 63) / 64)                // 1563
#define NCTA 296
#define WCHUNK 32

// named-barrier ids: FULL buf0/1 = 1/2, EMPTY buf0/1 = 3/4, consumer-internal = 5
#define BAR_SYNC(id, cnt)   asm volatile("bar.sync %0, %1;"   :: "r"(id), "r"(cnt) : "memory")
#define BAR_ARRIVE(id, cnt) asm volatile("bar.arrive %0, %1;" :: "r"(id), "r"(cnt) : "memory")

// Scratch (__device__ globals; no allocations allowed)
__device__ float g_h [NN * HH];
__device__ float g_h2[NN * HH];
__device__ int   g_off[NN + 1];
__device__ int   g_cur[NN];
__device__ int   g_csr[EE];
__device__ int   g_bsum[256];
__device__ int   g_bpre[256];
__device__ float g_gsum[GG * HH];
__device__ int   g_gcnt[GG];

// ---------------------------------------------------------------------------
__global__ void proj_kernel(const float* __restrict__ x,
                            const float* __restrict__ pw,
                            const float* __restrict__ pb,
                            float* __restrict__ h) {
    int n = blockIdx.x;
    int j = threadIdx.x;
    const float* xr = x + (size_t)n * 4;
    float acc = pb[j];
    acc += xr[0] * pw[0 * HH + j];
    acc += xr[1] * pw[1 * HH + j];
    acc += xr[2] * pw[2 * HH + j];
    acc += xr[3] * pw[3 * HH + j];
    h[(size_t)n * HH + j] = acc;
}

// ---------------------------------------------------------------------------
__global__ void zero_kernel(int* __restrict__ deg,
                            float* __restrict__ gsum, int* __restrict__ gcnt) {
    int i = blockIdx.x * blockDim.x + threadIdx.x;
    if (i <= NN) deg[i] = 0;
    if (i < GG * HH) gsum[i] = 0.f;
    if (i < GG) gcnt[i] = 0;
}

__global__ void hist_kernel(const int* __restrict__ ei, int* __restrict__ deg) {
    int e = blockIdx.x * blockDim.x + threadIdx.x;
    if (e < EE) atomicAdd(deg + __ldg(ei + EE + e), 1);
}

__global__ void scan1_kernel(int* __restrict__ off, int* __restrict__ bsum) {
    __shared__ int s[SCAN_B];
    int t = threadIdx.x;
    int i = blockIdx.x * SCAN_B + t;
    int v = (i < NN) ? off[i] : 0;
    s[t] = v;
    __syncthreads();
    for (int o = 1; o < SCAN_B; o <<= 1) {
        int x = (t >= o) ? s[t - o] : 0;
        __syncthreads();
        s[t] += x;
        __syncthreads();
    }
    if (i < NN) off[i] = s[t] - v;
    if (t == SCAN_B - 1) bsum[blockIdx.x] = s[t];
}

__global__ void scan2_kernel(const int* __restrict__ bsum, int* __restrict__ bpre) {
    __shared__ int s[256];
    int t = threadIdx.x;
    int v = (t < SCAN_NB) ? bsum[t] : 0;
    s[t] = v;
    __syncthreads();
    for (int o = 1; o < 256; o <<= 1) {
        int x = (t >= o) ? s[t - o] : 0;
        __syncthreads();
        s[t] += x;
        __syncthreads();
    }
    if (t < SCAN_NB) bpre[t] = s[t] - v;
}

__global__ void scan3_kernel(int* __restrict__ off, const int* __restrict__ bpre,
                             int* __restrict__ cur) {
    int i = blockIdx.x * blockDim.x + threadIdx.x;
    if (i < NN) {
        int o = off[i] + bpre[i / SCAN_B];
        off[i] = o;
        cur[i] = o;
    }
    if (i == NN) off[NN] = EE;
}

__global__ void fill_kernel(const int* __restrict__ ei,
                            int* __restrict__ cur, int* __restrict__ csr) {
    int e = blockIdx.x * blockDim.x + threadIdx.x;
    if (e < EE) {
        int s = __ldg(ei + e);
        int d = __ldg(ei + EE + e);
        int p = atomicAdd(cur + d, 1);
        csr[p] = s;
    }
}

// ---------------------------------------------------------------------------
// Warp-specialized fused layer kernel (persistent, strided tiles):
//   producers (warps 8-15, 256 thr): CSR gather of tile i into buf[i%2]
//   consumers (warps 0-7,  256 thr): MLP GEMMs on buf[i%2], write h_out
// Balanced 8/8 split; double-buffered via named barriers; 2 CTAs/SM.
// dyn smem: sW (WCHUNK*HH) + 2 tiles of 64*PITCH floats = 83968 B.
__global__ void __launch_bounds__(512, 2) mlp_ws_kernel(
    const float* __restrict__ in, float* __restrict__ out,
    const int* __restrict__ off, const int* __restrict__ csr,
    const float* __restrict__ W1, const float* __restrict__ B1,
    const float* __restrict__ W2, const float* __restrict__ B2) {
    extern __shared__ float smem[];
    float* sW  = smem;                   // WCHUNK*HH floats
    float* sMT = smem + WCHUNK * HH;     // 2 * 64*PITCH floats

    const int tid = threadIdx.x;

    if (tid >= 256) {
        // ---------------- producer: 8 warps, 8 rows each ----------------
        const int ptid = tid - 256;
        const int pw   = ptid >> 5;       // 0..7
        const int lane = ptid & 31;
        const float4* in4 = (const float4*)in;
        int i = 0;
        for (int tt = blockIdx.x; tt < NTILES; tt += NCTA, i++) {
            const int bi = i & 1;
            if (i >= 2) BAR_SYNC(3 + bi, 512);        // wait buffer empty
            float* buf = sMT + bi * (64 * PITCH);
            const int row0 = tt * 64;
#pragma unroll
            for (int jj = 0; jj < 4; jj++) {
                int r0 = pw * 8 + jj * 2;
                int n0 = row0 + r0;
                int n1 = n0 + 1;
                float4 a0 = make_float4(0.f, 0.f, 0.f, 0.f);
                float4 a1 = make_float4(0.f, 0.f, 0.f, 0.f);
                int d0 = 0, d1 = 0, s0 = 0, s1 = 0;
                if (n0 < NN) {
                    a0 = __ldg(in4 + (size_t)n0 * 32 + lane);
                    s0 = __ldg(off + n0);
                    d0 = __ldg(off + n0 + 1) - s0;
                }
                if (n1 < NN) {
                    a1 = __ldg(in4 + (size_t)n1 * 32 + lane);
                    s1 = __ldg(off + n1);
                    d1 = __ldg(off + n1 + 1) - s1;
                }
                int dmax = d0 > d1 ? d0 : d1;
#pragma unroll 4
                for (int e = 0; e < dmax; e++) {
                    if (e < d0) {                       // warp-uniform
                        int s = __ldg(csr + s0 + e);
                        float4 v = __ldg(in4 + (size_t)s * 32 + lane);
                        a0.x += v.x; a0.y += v.y; a0.z += v.z; a0.w += v.w;
                    }
                    if (e < d1) {                       // warp-uniform
                        int s = __ldg(csr + s1 + e);
                        float4 v = __ldg(in4 + (size_t)s * 32 + lane);
                        a1.x += v.x; a1.y += v.y; a1.z += v.z; a1.w += v.w;
                    }
                }
                *(float4*)(buf + r0 * PITCH + lane * 4)       = a0;
                *(float4*)(buf + (r0 + 1) * PITCH + lane * 4) = a1;
            }
            __threadfence_block();
            BAR_ARRIVE(1 + bi, 512);                   // signal buffer full
        }
    } else {
        // ---------------- consumer: 8 warps, 64x128 double-GEMM ----------------
        const int rb = tid >> 4;            // 0..15 -> rows rb*4+i
        const int cg = (tid & 15) * 8;      // 0..120 step 8
        int i = 0;
        for (int tt = blockIdx.x; tt < NTILES; tt += NCTA, i++) {
            const int bi = i & 1;
            BAR_SYNC(1 + bi, 512);                     // wait buffer full
            float* buf = sMT + bi * (64 * PITCH);
            const int row0 = tt * 64;

            float acc[4][8];
#pragma unroll
            for (int a = 0; a < 4; a++)
#pragma unroll
                for (int b = 0; b < 8; b++) acc[a][b] = 0.f;

            // ---- GEMM 1: t = m @ W1 ----
            for (int kc = 0; kc < HH; kc += WCHUNK) {
                BAR_SYNC(5, 256);
                for (int q = tid; q < WCHUNK * 32; q += 256)
                    ((float4*)sW)[q] = ((const float4*)(W1 + (size_t)kc * HH))[q];
                BAR_SYNC(5, 256);
#pragma unroll
                for (int k = 0; k < WCHUNK; k++) {
                    float4 w0 = *(const float4*)(sW + k * HH + cg);
                    float4 w1 = *(const float4*)(sW + k * HH + cg + 4);
#pragma unroll
                    for (int a = 0; a < 4; a++) {
                        float m = buf[(rb * 4 + a) * PITCH + kc + k];
                        acc[a][0] += m * w0.x; acc[a][1] += m * w0.y;
                        acc[a][2] += m * w0.z; acc[a][3] += m * w0.w;
                        acc[a][4] += m * w1.x; acc[a][5] += m * w1.y;
                        acc[a][6] += m * w1.z; acc[a][7] += m * w1.w;
                    }
                }
            }
            BAR_SYNC(5, 256);   // all m reads done before overwrite

            // t = relu(acc + b1) -> buf
            {
                float4 b0 = *(const float4*)(B1 + cg);
                float4 b1 = *(const float4*)(B1 + cg + 4);
#pragma unroll
                for (int a = 0; a < 4; a++) {
                    int r = rb * 4 + a;
                    float4 t0, t1;
                    t0.x = fmaxf(acc[a][0] + b0.x, 0.f);
                    t0.y = fmaxf(acc[a][1] + b0.y, 0.f);
                    t0.z = fmaxf(acc[a][2] + b0.z, 0.f);
                    t0.w = fmaxf(acc[a][3] + b0.w, 0.f);
                    t1.x = fmaxf(acc[a][4] + b1.x, 0.f);
                    t1.y = fmaxf(acc[a][5] + b1.y, 0.f);
                    t1.z = fmaxf(acc[a][6] + b1.z, 0.f);
                    t1.w = fmaxf(acc[a][7] + b1.w, 0.f);
                    *(float4*)(buf + r * PITCH + cg)     = t0;
                    *(float4*)(buf + r * PITCH + cg + 4) = t1;
#pragma unroll
                    for (int b = 0; b < 8; b++) acc[a][b] = 0.f;
                }
            }

            // ---- GEMM 2: o = t @ W2 ----
            for (int kc = 0; kc < HH; kc += WCHUNK) {
                BAR_SYNC(5, 256);
                for (int q = tid; q < WCHUNK * 32; q += 256)
                    ((float4*)sW)[q] = ((const float4*)(W2 + (size_t)kc * HH))[q];
                BAR_SYNC(5, 256);
#pragma unroll
                for (int k = 0; k < WCHUNK; k++) {
                    float4 w0 = *(const float4*)(sW + k * HH + cg);
                    float4 w1 = *(const float4*)(sW + k * HH + cg + 4);
#pragma unroll
                    for (int a = 0; a < 4; a++) {
                        float t = buf[(rb * 4 + a) * PITCH + kc + k];
                        acc[a][0] += t * w0.x; acc[a][1] += t * w0.y;
                        acc[a][2] += t * w0.z; acc[a][3] += t * w0.w;
                        acc[a][4] += t * w1.x; acc[a][5] += t * w1.y;
                        acc[a][6] += t * w1.z; acc[a][7] += t * w1.w;
                    }
                }
            }

            // h_out = relu(acc + b2)
            {
                float4 b0 = *(const float4*)(B2 + cg);
                float4 b1 = *(const float4*)(B2 + cg + 4);
#pragma unroll
                for (int a = 0; a < 4; a++) {
                    int n = row0 + rb * 4 + a;
                    if (n < NN) {
                        float4 o0, o1;
                        o0.x = fmaxf(acc[a][0] + b0.x, 0.f);
                        o0.y = fmaxf(acc[a][1] + b0.y, 0.f);
                        o0.z = fmaxf(acc[a][2] + b0.z, 0.f);
                        o0.w = fmaxf(acc[a][3] + b0.w, 0.f);
                        o1.x = fmaxf(acc[a][4] + b1.x, 0.f);
                        o1.y = fmaxf(acc[a][5] + b1.y, 0.f);
                        o1.z = fmaxf(acc[a][6] + b1.z, 0.f);
                        o1.w = fmaxf(acc[a][7] + b1.w, 0.f);
                        *(float4*)(out + (size_t)n * HH + cg)     = o0;
                        *(float4*)(out + (size_t)n * HH + cg + 4) = o1;
                    }
                }
            }
            BAR_ARRIVE(3 + bi, 512);                   // signal buffer empty
        }
    }
}

// ---------------------------------------------------------------------------
__global__ void pool_kernel(const float* __restrict__ h, const int* __restrict__ batch,
                            float* __restrict__ gsum, int* __restrict__ gcnt) {
    int n = (blockIdx.x * blockDim.x + threadIdx.x) >> 5;
    if (n >= NN) return;
    int lane = threadIdx.x & 31;
    int b = __ldg(batch + n);
    float4 v = ((const float4*)(h + (size_t)n * HH))[lane];
    float* dst = gsum + (size_t)b * HH + lane * 4;
    atomicAdd(dst + 0, v.x);
    atomicAdd(dst + 1, v.y);
    atomicAdd(dst + 2, v.z);
    atomicAdd(dst + 3, v.w);
    if (lane == 0) atomicAdd(gcnt + b, 1);
}

// ---------------------------------------------------------------------------
__global__ void head_kernel(const float* __restrict__ gsum, const int* __restrict__ gcnt,
                            const float* __restrict__ Ws, const float* __restrict__ Bs,
                            const float* __restrict__ ew, const float* __restrict__ eb,
                            const float* __restrict__ dw, const float* __restrict__ db,
                            float* __restrict__ out) {
    int g = blockIdx.x;
    int j = threadIdx.x;
    __shared__ float sg[HH];
    __shared__ float re[HH];
    __shared__ float rd[HH];

    float cnt = fmaxf((float)gcnt[g], 1.f);
    sg[j] = gsum[(size_t)g * HH + j] / cnt;
    __syncthreads();

    float a = Bs[j];
#pragma unroll 8
    for (int k = 0; k < HH; k++) a += sg[k] * Ws[k * HH + j];
    a = fmaxf(a, 0.f);

    re[j] = a * ew[j];
    rd[j] = a * dw[j];
    __syncthreads();
    for (int s = 64; s > 0; s >>= 1) {
        if (j < s) { re[j] += re[j + s]; rd[j] += rd[j + s]; }
        __syncthreads();
    }
    if (j == 0) {
        out[g]      = re[0] + eb[0];
        out[GG + g] = rd[0] + db[0];
    }
}

// ---------------------------------------------------------------------------
extern "C" void kernel_launch(void* const* d_in, const int* in_sizes, int n_in,
                              void* d_out, int out_size) {
    const float* x       = (const float*)d_in[0];
    const int*   ei      = (const int*)  d_in[1];
    const int*   batch   = (const int*)  d_in[2];
    const float* proj_w  = (const float*)d_in[3];
    const float* proj_b  = (const float*)d_in[4];
    const float* conv_w1 = (const float*)d_in[5];
    const float* conv_b1 = (const float*)d_in[6];
    const float* conv_w2 = (const float*)d_in[7];
    const float* conv_b2 = (const float*)d_in[8];
    const float* sh_w    = (const float*)d_in[9];
    const float* sh_b    = (const float*)d_in[10];
    const float* e_w     = (const float*)d_in[11];
    const float* e_b     = (const float*)d_in[12];
    const float* d_w     = (const float*)d_in[13];
    const float* d_b     = (const float*)d_in[14];
    float* out = (float*)d_out;

    float *h, *h2, *gsum;
    int *off, *cur, *csr, *bsum, *bpre, *gcnt;
    cudaGetSymbolAddress((void**)&h,    g_h);
    cudaGetSymbolAddress((void**)&h2,   g_h2);
    cudaGetSymbolAddress((void**)&off,  g_off);
    cudaGetSymbolAddress((void**)&cur,  g_cur);
    cudaGetSymbolAddress((void**)&csr,  g_csr);
    cudaGetSymbolAddress((void**)&bsum, g_bsum);
    cudaGetSymbolAddress((void**)&bpre, g_bpre);
    cudaGetSymbolAddress((void**)&gsum, g_gsum);
    cudaGetSymbolAddress((void**)&gcnt, g_gcnt);

    static int smem_set = 0;
    const int DYN_SMEM = (WCHUNK * HH + 2 * 64 * PITCH) * (int)sizeof(float);  // 83968
    if (!smem_set) {
        cudaFuncSetAttribute(mlp_ws_kernel,
                             cudaFuncAttributeMaxDynamicSharedMemorySize, DYN_SMEM);
        smem_set = 1;
    }

    // input projection
    proj_kernel<<<NN, HH>>>(x, proj_w, proj_b, h);

    // CSR build (edges grouped by destination); deg accumulates in off[]
    zero_kernel<<<(GG * HH + 255) / 256, 256>>>(off, gsum, gcnt);
    hist_kernel<<<(EE + 255) / 256, 256>>>(ei, off);
    scan1_kernel<<<SCAN_NB, SCAN_B>>>(off, bsum);
    scan2_kernel<<<1, 256>>>(bsum, bpre);
    scan3_kernel<<<(NN + 256) / 256, 256>>>(off, bpre, cur);
    fill_kernel<<<(EE + 255) / 256, 256>>>(ei, cur, csr);

    // GIN layers (warp-specialized fused gather+MLP; ping-pong h <-> h2)
    const float* src = h;
    float* dst = h2;
    for (int l = 0; l < LL; l++) {
        mlp_ws_kernel<<<NCTA, 512, DYN_SMEM>>>(src, dst, off, csr,
                                               conv_w1 + (size_t)l * HH * HH,
                                               conv_b1 + (size_t)l * HH,
                                               conv_w2 + (size_t)l * HH * HH,
                                               conv_b2 + (size_t)l * HH);
        const float* t = dst; dst = (float*)src; src = t;
    }
    const float* hf = src;   // final features

    pool_kernel<<<(NN * 32 + 255) / 256, 256>>>(hf, batch, gsum, gcnt);
    head_kernel<<<GG, HH>>>(gsum, gcnt, sh_w, sh_b, e_w, e_b, d_w, d_b, out);
}

// round 10
// speedup vs baseline: 1.0111x; 1.0037x over previous
#include <cuda_runtime.h>
#include <cuda_bf16.h>

#define NN 100000
#define EE 1600000
#define GG 2000
#define HH 128
#define LL 3
#define SCAN_B 512
#define SCAN_NB ((NN + SCAN_B - 1) / SCAN_B)   // 196
#define PITCH 132   // 4*PITCH % 32 == 16 -> row-groups 4 apart hit different banks
#define CAP 2048    // staged csr indices per 64-row tile (mean ~1024, sigma ~32)

// Scratch (__device__ globals; no allocations allowed)
__device__ float g_h [NN * HH];
__device__ float g_h2[NN * HH];
__device__ int   g_off[NN + 1];
__device__ int   g_cur[NN];
__device__ int   g_csr[EE];
__device__ int   g_bsum[256];
__device__ int   g_bpre[256];
__device__ float g_gsum[GG * HH];
__device__ int   g_gcnt[GG];

// ---------------------------------------------------------------------------
__global__ void proj_kernel(const float* __restrict__ x,
                            const float* __restrict__ pw,
                            const float* __restrict__ pb,
                            float* __restrict__ h) {
    int n = blockIdx.x;
    int j = threadIdx.x;
    const float* xr = x + (size_t)n * 4;
    float acc = pb[j];
    acc += xr[0] * pw[0 * HH + j];
    acc += xr[1] * pw[1 * HH + j];
    acc += xr[2] * pw[2 * HH + j];
    acc += xr[3] * pw[3 * HH + j];
    h[(size_t)n * HH + j] = acc;
}

// ---------------------------------------------------------------------------
__global__ void zero_kernel(int* __restrict__ deg,
                            float* __restrict__ gsum, int* __restrict__ gcnt) {
    int i = blockIdx.x * blockDim.x + threadIdx.x;
    if (i <= NN) deg[i] = 0;
    if (i < GG * HH) gsum[i] = 0.f;
    if (i < GG) gcnt[i] = 0;
}

__global__ void hist_kernel(const int* __restrict__ ei, int* __restrict__ deg) {
    int e = blockIdx.x * blockDim.x + threadIdx.x;
    if (e < EE) atomicAdd(deg + __ldg(ei + EE + e), 1);
}

__global__ void scan1_kernel(int* __restrict__ off, int* __restrict__ bsum) {
    __shared__ int s[SCAN_B];
    int t = threadIdx.x;
    int i = blockIdx.x * SCAN_B + t;
    int v = (i < NN) ? off[i] : 0;
    s[t] = v;
    __syncthreads();
    for (int o = 1; o < SCAN_B; o <<= 1) {
        int x = (t >= o) ? s[t - o] : 0;
        __syncthreads();
        s[t] += x;
        __syncthreads();
    }
    if (i < NN) off[i] = s[t] - v;
    if (t == SCAN_B - 1) bsum[blockIdx.x] = s[t];
}

__global__ void scan2_kernel(const int* __restrict__ bsum, int* __restrict__ bpre) {
    __shared__ int s[256];
    int t = threadIdx.x;
    int v = (t < SCAN_NB) ? bsum[t] : 0;
    s[t] = v;
    __syncthreads();
    for (int o = 1; o < 256; o <<= 1) {
        int x = (t >= o) ? s[t - o] : 0;
        __syncthreads();
        s[t] += x;
        __syncthreads();
    }
    if (t < SCAN_NB) bpre[t] = s[t] - v;
}

__global__ void scan3_kernel(int* __restrict__ off, const int* __restrict__ bpre,
                             int* __restrict__ cur) {
    int i = blockIdx.x * blockDim.x + threadIdx.x;
    if (i < NN) {
        int o = off[i] + bpre[i / SCAN_B];
        off[i] = o;
        cur[i] = o;
    }
    if (i == NN) off[NN] = EE;
}

__global__ void fill_kernel(const int* __restrict__ ei,
                            int* __restrict__ cur, int* __restrict__ csr) {
    int e = blockIdx.x * blockDim.x + threadIdx.x;
    if (e < EE) {
        int s = __ldg(ei + e);
        int d = __ldg(ei + EE + e);
        int p = atomicAdd(cur + d, 1);
        csr[p] = s;
    }
}

// ---------------------------------------------------------------------------
// Fused layer kernel with SMEM-STAGED CSR indices:
//   1) stage csr[off[row0]..off[row0+64]) + 65 offsets into smem (coalesced)
//   2) gather m = h + sum_nbr h into smem tile (indices via LDS -> high MLP)
//   3) h_out = relu( relu(m @ W1 + b1) @ W2 + b2 )
// 64-row tile, 256 threads, 4 CTAs/SM. dyn smem ~50.4 KB.
__global__ void __launch_bounds__(256, 4) mlp_fused_kernel(
    const float* __restrict__ in, float* __restrict__ out,
    const int* __restrict__ off, const int* __restrict__ csr,
    const float* __restrict__ W1, const float* __restrict__ B1,
    const float* __restrict__ W2, const float* __restrict__ B2) {
    extern __shared__ float smem[];
    float* sMT = smem;                       // 64*PITCH floats
    float* sW  = smem + 64 * PITCH;          // 16*HH floats
    int*   sidx = (int*)(sW + 16 * HH);      // CAP ints
    int*   soff = sidx + CAP;                // 65 ints

    int tid  = threadIdx.x;
    int lane = tid & 31;
    int wrp  = tid >> 5;
    int row0 = blockIdx.x * 64;
    const float4* in4 = (const float4*)in;

    // ---- stage offsets + csr segment ----
    if (tid < 65) {
        int n = row0 + tid;
        soff[tid] = __ldg(off + (n < NN ? n : NN));
    }
    __syncthreads();
    int base = soff[0];
    int cnt  = soff[64] - base;
    int cc   = cnt < CAP ? cnt : CAP;
    for (int i = tid; i < cc; i += 256)
        sidx[i] = __ldg(csr + base + i);
    __syncthreads();

    // ---- gather phase: warp wrp handles rows wrp*8..wrp*8+7 ----
#pragma unroll
    for (int j = 0; j < 8; j++) {
        int r = wrp * 8 + j;
        int n = row0 + r;
        float4 a = make_float4(0.f, 0.f, 0.f, 0.f);
        if (n < NN) {
            a = __ldg(in4 + (size_t)n * 32 + lane);
            int e0 = soff[r] - base;
            int e1 = soff[r + 1] - base;
#pragma unroll 4
            for (int e = e0; e < e1; e++) {
                int s = (e < CAP) ? sidx[e] : __ldg(csr + base + e);
                float4 v = __ldg(in4 + (size_t)s * 32 + lane);
                a.x += v.x; a.y += v.y; a.z += v.z; a.w += v.w;
            }
        }
        *(float4*)(sMT + r * PITCH + lane * 4) = a;
    }

    int rb = tid >> 4;            // 0..15  -> rows rb*4 .. rb*4+3
    int cg = (tid & 15) * 8;      // 0..120 step 8

    float acc[4][8];
#pragma unroll
    for (int i = 0; i < 4; i++)
#pragma unroll
        for (int j = 0; j < 8; j++) acc[i][j] = 0.f;

    // ---- GEMM 1: t = m @ W1 ----
    for (int kc = 0; kc < HH; kc += 16) {
        __syncthreads();
        for (int i = tid; i < 16 * 32; i += 256)
            ((float4*)sW)[i] = ((const float4*)(W1 + (size_t)kc * HH))[i];
        __syncthreads();
#pragma unroll
        for (int k = 0; k < 16; k++) {
            float4 w0 = *(const float4*)(sW + k * HH + cg);
            float4 w1 = *(const float4*)(sW + k * HH + cg + 4);
#pragma unroll
            for (int i = 0; i < 4; i++) {
                float m = sMT[(rb * 4 + i) * PITCH + kc + k];
                acc[i][0] += m * w0.x; acc[i][1] += m * w0.y;
                acc[i][2] += m * w0.z; acc[i][3] += m * w0.w;
                acc[i][4] += m * w1.x; acc[i][5] += m * w1.y;
                acc[i][6] += m * w1.z; acc[i][7] += m * w1.w;
            }
        }
    }
    __syncthreads();

    // t = relu(acc + b1) -> sMT
    {
        float4 b0 = *(const float4*)(B1 + cg);
        float4 b1 = *(const float4*)(B1 + cg + 4);
#pragma unroll
        for (int i = 0; i < 4; i++) {
            int r = rb * 4 + i;
            float4 t0, t1;
            t0.x = fmaxf(acc[i][0] + b0.x, 0.f);
            t0.y = fmaxf(acc[i][1] + b0.y, 0.f);
            t0.z = fmaxf(acc[i][2] + b0.z, 0.f);
            t0.w = fmaxf(acc[i][3] + b0.w, 0.f);
            t1.x = fmaxf(acc[i][4] + b1.x, 0.f);
            t1.y = fmaxf(acc[i][5] + b1.y, 0.f);
            t1.z = fmaxf(acc[i][6] + b1.z, 0.f);
            t1.w = fmaxf(acc[i][7] + b1.w, 0.f);
            *(float4*)(sMT + r * PITCH + cg)     = t0;
            *(float4*)(sMT + r * PITCH + cg + 4) = t1;
#pragma unroll
            for (int j = 0; j < 8; j++) acc[i][j] = 0.f;
        }
    }

    // ---- GEMM 2: o = t @ W2 ----
    for (int kc = 0; kc < HH; kc += 16) {
        __syncthreads();
        for (int i = tid; i < 16 * 32; i += 256)
            ((float4*)sW)[i] = ((const float4*)(W2 + (size_t)kc * HH))[i];
        __syncthreads();
#pragma unroll
        for (int k = 0; k < 16; k++) {
            float4 w0 = *(const float4*)(sW + k * HH + cg);
            float4 w1 = *(const float4*)(sW + k * HH + cg + 4);
#pragma unroll
            for (int i = 0; i < 4; i++) {
                float t = sMT[(rb * 4 + i) * PITCH + kc + k];
                acc[i][0] += t * w0.x; acc[i][1] += t * w0.y;
                acc[i][2] += t * w0.z; acc[i][3] += t * w0.w;
                acc[i][4] += t * w1.x; acc[i][5] += t * w1.y;
                acc[i][6] += t * w1.z; acc[i][7] += t * w1.w;
            }
        }
    }

    // h_out = relu(acc + b2)
    {
        float4 b0 = *(const float4*)(B2 + cg);
        float4 b1 = *(const float4*)(B2 + cg + 4);
#pragma unroll
        for (int i = 0; i < 4; i++) {
            int n = row0 + rb * 4 + i;
            if (n < NN) {
                float4 o0, o1;
                o0.x = fmaxf(acc[i][0] + b0.x, 0.f);
                o0.y = fmaxf(acc[i][1] + b0.y, 0.f);
                o0.z = fmaxf(acc[i][2] + b0.z, 0.f);
                o0.w = fmaxf(acc[i][3] + b0.w, 0.f);
                o1.x = fmaxf(acc[i][4] + b1.x, 0.f);
                o1.y = fmaxf(acc[i][5] + b1.y, 0.f);
                o1.z = fmaxf(acc[i][6] + b1.z, 0.f);
                o1.w = fmaxf(acc[i][7] + b1.w, 0.f);
                *(float4*)(out + (size_t)n * HH + cg)     = o0;
                *(float4*)(out + (size_t)n * HH + cg + 4) = o1;
            }
        }
    }
}

// ---------------------------------------------------------------------------
__global__ void pool_kernel(const float* __restrict__ h, const int* __restrict__ batch,
                            float* __restrict__ gsum, int* __restrict__ gcnt) {
    int n = (blockIdx.x * blockDim.x + threadIdx.x) >> 5;
    if (n >= NN) return;
    int lane = threadIdx.x & 31;
    int b = __ldg(batch + n);
    float4 v = ((const float4*)(h + (size_t)n * HH))[lane];
    float* dst = gsum + (size_t)b * HH + lane * 4;
    atomicAdd(dst + 0, v.x);
    atomicAdd(dst + 1, v.y);
    atomicAdd(dst + 2, v.z);
    atomicAdd(dst + 3, v.w);
    if (lane == 0) atomicAdd(gcnt + b, 1);
}

// ---------------------------------------------------------------------------
__global__ void head_kernel(const float* __restrict__ gsum, const int* __restrict__ gcnt,
                            const float* __restrict__ Ws, const float* __restrict__ Bs,
                            const float* __restrict__ ew, const float* __restrict__ eb,
                            const float* __restrict__ dw, const float* __restrict__ db,
                            float* __restrict__ out) {
    int g = blockIdx.x;
    int j = threadIdx.x;
    __shared__ float sg[HH];
    __shared__ float re[HH];
    __shared__ float rd[HH];

    float cnt = fmaxf((float)gcnt[g], 1.f);
    sg[j] = gsum[(size_t)g * HH + j] / cnt;
    __syncthreads();

    float a = Bs[j];
#pragma unroll 8
    for (int k = 0; k < HH; k++) a += sg[k] * Ws[k * HH + j];
    a = fmaxf(a, 0.f);

    re[j] = a * ew[j];
    rd[j] = a * dw[j];
    __syncthreads();
    for (int s = 64; s > 0; s >>= 1) {
        if (j < s) { re[j] += re[j + s]; rd[j] += rd[j + s]; }
        __syncthreads();
    }
    if (j == 0) {
        out[g]      = re[0] + eb[0];
        out[GG + g] = rd[0] + db[0];
    }
}

// ---------------------------------------------------------------------------
extern "C" void kernel_launch(void* const* d_in, const int* in_sizes, int n_in,
                              void* d_out, int out_size) {
    const float* x       = (const float*)d_in[0];
    const int*   ei      = (const int*)  d_in[1];
    const int*   batch   = (const int*)  d_in[2];
    const float* proj_w  = (const float*)d_in[3];
    const float* proj_b  = (const float*)d_in[4];
    const float* conv_w1 = (const float*)d_in[5];
    const float* conv_b1 = (const float*)d_in[6];
    const float* conv_w2 = (const float*)d_in[7];
    const float* conv_b2 = (const float*)d_in[8];
    const float* sh_w    = (const float*)d_in[9];
    const float* sh_b    = (const float*)d_in[10];
    const float* e_w     = (const float*)d_in[11];
    const float* e_b     = (const float*)d_in[12];
    const float* d_w     = (const float*)d_in[13];
    const float* d_b     = (const float*)d_in[14];
    float* out = (float*)d_out;

    float *h, *h2, *gsum;
    int *off, *cur, *csr, *bsum, *bpre, *gcnt;
    cudaGetSymbolAddress((void**)&h,    g_h);
    cudaGetSymbolAddress((void**)&h2,   g_h2);
    cudaGetSymbolAddress((void**)&off,  g_off);
    cudaGetSymbolAddress((void**)&cur,  g_cur);
    cudaGetSymbolAddress((void**)&csr,  g_csr);
    cudaGetSymbolAddress((void**)&bsum, g_bsum);
    cudaGetSymbolAddress((void**)&bpre, g_bpre);
    cudaGetSymbolAddress((void**)&gsum, g_gsum);
    cudaGetSymbolAddress((void**)&gcnt, g_gcnt);

    static int smem_set = 0;
    const int DYN_SMEM = (64 * PITCH + 16 * HH) * (int)sizeof(float)
                       + (CAP + 65) * (int)sizeof(int);   // ~50.4 KB
    if (!smem_set) {
        cudaFuncSetAttribute(mlp_fused_kernel,
                             cudaFuncAttributeMaxDynamicSharedMemorySize, DYN_SMEM);
        smem_set = 1;
    }

    // input projection
    proj_kernel<<<NN, HH>>>(x, proj_w, proj_b, h);

    // CSR build (edges grouped by destination); deg accumulates in off[]
    zero_kernel<<<(GG * HH + 255) / 256, 256>>>(off, gsum, gcnt);
    hist_kernel<<<(EE + 255) / 256, 256>>>(ei, off);
    scan1_kernel<<<SCAN_NB, SCAN_B>>>(off, bsum);
    scan2_kernel<<<1, 256>>>(bsum, bpre);
    scan3_kernel<<<(NN + 256) / 256, 256>>>(off, bpre, cur);
    fill_kernel<<<(EE + 255) / 256, 256>>>(ei, cur, csr);

    // GIN layers (fused staged-gather + MLP; ping-pong h <-> h2)
    const int mlp_blocks = (NN + 63) / 64;
    const float* src = h;
    float* dst = h2;
    for (int l = 0; l < LL; l++) {
        mlp_fused_kernel<<<mlp_blocks, 256, DYN_SMEM>>>(src, dst, off, csr,
                                              conv_w1 + (size_t)l * HH * HH,
                                              conv_b1 + (size_t)l * HH,
                                              conv_w2 + (size_t)l * HH * HH,
                                              conv_b2 + (size_t)l * HH);
        const float* t = dst; dst = (float*)src; src = t;
    }
    const float* hf = src;   // final features

    pool_kernel<<<(NN * 32 + 255) / 256, 256>>>(hf, batch, gsum, gcnt);
    head_kernel<<<GG, HH>>>(gsum, gcnt, sh_w, sh_b, e_w, e_b, d_w, d_b, out);
}

// round 12
// speedup vs baseline: 1.0562x; 1.0447x over previous
#include <cuda_runtime.h>
#include <cuda_bf16.h>

#define NN 100000
#define EE 1600000
#define GG 2000
#define HH 128
#define LL 3
#define SCAN_B 512
#define SCAN_NB ((NN + SCAN_B - 1) / SCAN_B)   // 196
#define PITCH 132   // 4*PITCH % 32 == 16 -> row-groups 4 apart hit different banks

// Scratch (__device__ globals; no allocations allowed)
__device__ float g_h [NN * HH];
__device__ float g_h2[NN * HH];
__device__ int   g_off[NN + 1];
__device__ int   g_cur[NN];
__device__ int   g_csr[EE];
__device__ int   g_bsum[256];
__device__ int   g_bpre[256];
__device__ float g_gsum[GG * HH];
__device__ int   g_gcnt[GG];

// ---- packed f32x2 helpers (register-pure asm only; loads stay in C++) ----
#define FFMA2(acc, a, b) \
    asm("fma.rn.f32x2 %0, %1, %2, %0;" : "+l"(acc) : "l"(a), "l"(b))
#define PACK2F(out, lo, hi) \
    asm("mov.b64 %0, {%1, %2};" : "=l"(out) \
        : "r"(__float_as_uint(lo)), "r"(__float_as_uint(hi)))
#define UNPACK2(lo, hi, in) \
    asm("mov.b64 {%0, %1}, %2;" : "=r"(lo), "=r"(hi) : "l"(in))

// ---------------------------------------------------------------------------
__global__ void proj_kernel(const float* __restrict__ x,
                            const float* __restrict__ pw,
                            const float* __restrict__ pb,
                            float* __restrict__ h) {
    int n = blockIdx.x;
    int j = threadIdx.x;
    const float* xr = x + (size_t)n * 4;
    float acc = pb[j];
    acc += xr[0] * pw[0 * HH + j];
    acc += xr[1] * pw[1 * HH + j];
    acc += xr[2] * pw[2 * HH + j];
    acc += xr[3] * pw[3 * HH + j];
    h[(size_t)n * HH + j] = acc;
}

// ---------------------------------------------------------------------------
__global__ void zero_kernel(int* __restrict__ deg,
                            float* __restrict__ gsum, int* __restrict__ gcnt) {
    int i = blockIdx.x * blockDim.x + threadIdx.x;
    if (i <= NN) deg[i] = 0;
    if (i < GG * HH) gsum[i] = 0.f;
    if (i < GG) gcnt[i] = 0;
}

__global__ void hist_kernel(const int* __restrict__ ei, int* __restrict__ deg) {
    int e = blockIdx.x * blockDim.x + threadIdx.x;
    if (e < EE) atomicAdd(deg + __ldg(ei + EE + e), 1);
}

__global__ void scan1_kernel(int* __restrict__ off, int* __restrict__ bsum) {
    __shared__ int s[SCAN_B];
    int t = threadIdx.x;
    int i = blockIdx.x * SCAN_B + t;
    int v = (i < NN) ? off[i] : 0;
    s[t] = v;
    __syncthreads();
    for (int o = 1; o < SCAN_B; o <<= 1) {
        int x = (t >= o) ? s[t - o] : 0;
        __syncthreads();
        s[t] += x;
        __syncthreads();
    }
    if (i < NN) off[i] = s[t] - v;
    if (t == SCAN_B - 1) bsum[blockIdx.x] = s[t];
}

__global__ void scan2_kernel(const int* __restrict__ bsum, int* __restrict__ bpre) {
    __shared__ int s[256];
    int t = threadIdx.x;
    int v = (t < SCAN_NB) ? bsum[t] : 0;
    s[t] = v;
    __syncthreads();
    for (int o = 1; o < 256; o <<= 1) {
        int x = (t >= o) ? s[t - o] : 0;
        __syncthreads();
        s[t] += x;
        __syncthreads();
    }
    if (t < SCAN_NB) bpre[t] = s[t] - v;
}

__global__ void scan3_kernel(int* __restrict__ off, const int* __restrict__ bpre,
                             int* __restrict__ cur) {
    int i = blockIdx.x * blockDim.x + threadIdx.x;
    if (i < NN) {
        int o = off[i] + bpre[i / SCAN_B];
        off[i] = o;
        cur[i] = o;
    }
    if (i == NN) off[NN] = EE;
}

__global__ void fill_kernel(const int* __restrict__ ei,
                            int* __restrict__ cur, int* __restrict__ csr) {
    int e = blockIdx.x * blockDim.x + threadIdx.x;
    if (e < EE) {
        int s = __ldg(ei + e);
        int d = __ldg(ei + EE + e);
        int p = atomicAdd(cur + d, 1);
        csr[p] = s;
    }
}

// ---------------------------------------------------------------------------
// Fused: gather (m = h + sum_nbr h) into smem tile, then
//        h_out = relu( relu(m @ W1 + b1) @ W2 + b2 )  via packed f32x2 FMA.
// 64-row tile, 256 threads, 4 CTAs/SM.
// GEMM: thread (rb=tid>>4, cg=(tid&15)*8) owns rows rb*4+i (i<4),
// col-pairs -> acc2[4][4] (each = 2 packed fp32). W loads are plain C++
// float4 reads (compiler-visible memory deps); only reg-pure asm used.
__global__ void __launch_bounds__(256, 4) mlp_fused_kernel(
    const float* __restrict__ in, float* __restrict__ out,
    const int* __restrict__ off, const int* __restrict__ csr,
    const float* __restrict__ W1, const float* __restrict__ B1,
    const float* __restrict__ W2, const float* __restrict__ B2) {
    __shared__ float sMT[64 * PITCH];
    __shared__ float sW[16 * HH];

    int tid  = threadIdx.x;
    int lane = tid & 31;
    int wrp  = tid >> 5;
    int row0 = blockIdx.x * 64;
    const float4* in4 = (const float4*)in;

    // ---- gather phase: 4 pairs of rows, interleaved edge loops ----
#pragma unroll
    for (int jj = 0; jj < 4; jj++) {
        int r0 = wrp * 8 + jj * 2;
        int n0 = row0 + r0;
        int n1 = n0 + 1;
        float4 a0 = make_float4(0.f, 0.f, 0.f, 0.f);
        float4 a1 = make_float4(0.f, 0.f, 0.f, 0.f);
        int d0 = 0, d1 = 0, s0 = 0, s1 = 0;
        if (n0 < NN) {
            a0 = __ldg(in4 + (size_t)n0 * 32 + lane);
            s0 = __ldg(off + n0);
            d0 = __ldg(off + n0 + 1) - s0;
        }
        if (n1 < NN) {
            a1 = __ldg(in4 + (size_t)n1 * 32 + lane);
            s1 = __ldg(off + n1);
            d1 = __ldg(off + n1 + 1) - s1;
        }
        int dmax = d0 > d1 ? d0 : d1;
#pragma unroll 4
        for (int e = 0; e < dmax; e++) {
            if (e < d0) {            // warp-uniform branch
                int s = __ldg(csr + s0 + e);
                float4 v = __ldg(in4 + (size_t)s * 32 + lane);
                a0.x += v.x; a0.y += v.y; a0.z += v.z; a0.w += v.w;
            }
            if (e < d1) {            // warp-uniform branch
                int s = __ldg(csr + s1 + e);
                float4 v = __ldg(in4 + (size_t)s * 32 + lane);
                a1.x += v.x; a1.y += v.y; a1.z += v.z; a1.w += v.w;
            }
        }
        *(float4*)(sMT + r0 * PITCH + lane * 4)       = a0;
        *(float4*)(sMT + (r0 + 1) * PITCH + lane * 4) = a1;
    }

    int rb = tid >> 4;            // 0..15  -> rows rb*4 .. rb*4+3
    int cg = (tid & 15) * 8;      // 0..120 step 8

    unsigned long long acc2[4][4];
#pragma unroll
    for (int i = 0; i < 4; i++)
#pragma unroll
        for (int j = 0; j < 4; j++) acc2[i][j] = 0ULL;

    // ---- GEMM 1: t = m @ W1 ----
    for (int kc = 0; kc < HH; kc += 16) {
        __syncthreads();
        for (int i = tid; i < 16 * 32; i += 256)
            ((float4*)sW)[i] = ((const float4*)(W1 + (size_t)kc * HH))[i];
        __syncthreads();
#pragma unroll
        for (int k = 0; k < 16; k++) {
            float4 w0 = *(const float4*)(sW + k * HH + cg);
            float4 w1 = *(const float4*)(sW + k * HH + cg + 4);
            unsigned long long w01, w23, w45, w67;
            PACK2F(w01, w0.x, w0.y);
            PACK2F(w23, w0.z, w0.w);
            PACK2F(w45, w1.x, w1.y);
            PACK2F(w67, w1.z, w1.w);
#pragma unroll
            for (int i = 0; i < 4; i++) {
                float m = sMT[(rb * 4 + i) * PITCH + kc + k];
                unsigned long long m2;
                PACK2F(m2, m, m);
                FFMA2(acc2[i][0], m2, w01);
                FFMA2(acc2[i][1], m2, w23);
                FFMA2(acc2[i][2], m2, w45);
                FFMA2(acc2[i][3], m2, w67);
            }
        }
    }
    __syncthreads();

    // t = relu(acc + b1) -> sMT
    {
#pragma unroll
        for (int i = 0; i < 4; i++) {
            int r = rb * 4 + i;
            float v[8];
#pragma unroll
            for (int j = 0; j < 4; j++) {
                unsigned int lo, hi;
                UNPACK2(lo, hi, acc2[i][j]);
                v[2 * j]     = __uint_as_float(lo);
                v[2 * j + 1] = __uint_as_float(hi);
                acc2[i][j] = 0ULL;
            }
            float4 t0, t1;
            t0.x = fmaxf(v[0] + B1[cg],     0.f);
            t0.y = fmaxf(v[1] + B1[cg + 1], 0.f);
            t0.z = fmaxf(v[2] + B1[cg + 2], 0.f);
            t0.w = fmaxf(v[3] + B1[cg + 3], 0.f);
            t1.x = fmaxf(v[4] + B1[cg + 4], 0.f);
            t1.y = fmaxf(v[5] + B1[cg + 5], 0.f);
            t1.z = fmaxf(v[6] + B1[cg + 6], 0.f);
            t1.w = fmaxf(v[7] + B1[cg + 7], 0.f);
            *(float4*)(sMT + r * PITCH + cg)     = t0;
            *(float4*)(sMT + r * PITCH + cg + 4) = t1;
        }
    }

    // ---- GEMM 2: o = t @ W2 ----
    for (int kc = 0; kc < HH; kc += 16) {
        __syncthreads();
        for (int i = tid; i < 16 * 32; i += 256)
            ((float4*)sW)[i] = ((const float4*)(W2 + (size_t)kc * HH))[i];
        __syncthreads();
#pragma unroll
        for (int k = 0; k < 16; k++) {
            float4 w0 = *(const float4*)(sW + k * HH + cg);
            float4 w1 = *(const float4*)(sW + k * HH + cg + 4);
            unsigned long long w01, w23, w45, w67;
            PACK2F(w01, w0.x, w0.y);
            PACK2F(w23, w0.z, w0.w);
            PACK2F(w45, w1.x, w1.y);
            PACK2F(w67, w1.z, w1.w);
#pragma unroll
            for (int i = 0; i < 4; i++) {
                float t = sMT[(rb * 4 + i) * PITCH + kc + k];
                unsigned long long t2;
                PACK2F(t2, t, t);
                FFMA2(acc2[i][0], t2, w01);
                FFMA2(acc2[i][1], t2, w23);
                FFMA2(acc2[i][2], t2, w45);
                FFMA2(acc2[i][3], t2, w67);
            }
        }
    }

    // h_out = relu(acc + b2)
    {
#pragma unroll
        for (int i = 0; i < 4; i++) {
            int n = row0 + rb * 4 + i;
            if (n < NN) {
                float v[8];
#pragma unroll
                for (int j = 0; j < 4; j++) {
                    unsigned int lo, hi;
                    UNPACK2(lo, hi, acc2[i][j]);
                    v[2 * j]     = __uint_as_float(lo);
                    v[2 * j + 1] = __uint_as_float(hi);
                }
                float4 o0, o1;
                o0.x = fmaxf(v[0] + B2[cg],     0.f);
                o0.y = fmaxf(v[1] + B2[cg + 1], 0.f);
                o0.z = fmaxf(v[2] + B2[cg + 2], 0.f);
                o0.w = fmaxf(v[3] + B2[cg + 3], 0.f);
                o1.x = fmaxf(v[4] + B2[cg + 4], 0.f);
                o1.y = fmaxf(v[5] + B2[cg + 5], 0.f);
                o1.z = fmaxf(v[6] + B2[cg + 6], 0.f);
                o1.w = fmaxf(v[7] + B2[cg + 7], 0.f);
                *(float4*)(out + (size_t)n * HH + cg)     = o0;
                *(float4*)(out + (size_t)n * HH + cg + 4) = o1;
            }
        }
    }
}

// ---------------------------------------------------------------------------
__global__ void pool_kernel(const float* __restrict__ h, const int* __restrict__ batch,
                            float* __restrict__ gsum, int* __restrict__ gcnt) {
    int n = (blockIdx.x * blockDim.x + threadIdx.x) >> 5;
    if (n >= NN) return;
    int lane = threadIdx.x & 31;
    int b = __ldg(batch + n);
    float4 v = ((const float4*)(h + (size_t)n * HH))[lane];
    float* dst = gsum + (size_t)b * HH + lane * 4;
    atomicAdd(dst + 0, v.x);
    atomicAdd(dst + 1, v.y);
    atomicAdd(dst + 2, v.z);
    atomicAdd(dst + 3, v.w);
    if (lane == 0) atomicAdd(gcnt + b, 1);
}

// ---------------------------------------------------------------------------
__global__ void head_kernel(const float* __restrict__ gsum, const int* __restrict__ gcnt,
                            const float* __restrict__ Ws, const float* __restrict__ Bs,
                            const float* __restrict__ ew, const float* __restrict__ eb,
                            const float* __restrict__ dw, const float* __restrict__ db,
                            float* __restrict__ out) {
    int g = blockIdx.x;
    int j = threadIdx.x;
    __shared__ float sg[HH];
    __shared__ float re[HH];
    __shared__ float rd[HH];

    float cnt = fmaxf((float)gcnt[g], 1.f);
    sg[j] = gsum[(size_t)g * HH + j] / cnt;
    __syncthreads();

    float a = Bs[j];
#pragma unroll 8
    for (int k = 0; k < HH; k++) a += sg[k] * Ws[k * HH + j];
    a = fmaxf(a, 0.f);

    re[j] = a * ew[j];
    rd[j] = a * dw[j];
    __syncthreads();
    for (int s = 64; s > 0; s >>= 1) {
        if (j < s) { re[j] += re[j + s]; rd[j] += rd[j + s]; }
        __syncthreads();
    }
    if (j == 0) {
        out[g]      = re[0] + eb[0];
        out[GG + g] = rd[0] + db[0];
    }
}

// ---------------------------------------------------------------------------
extern "C" void kernel_launch(void* const* d_in, const int* in_sizes, int n_in,
                              void* d_out, int out_size) {
    const float* x       = (const float*)d_in[0];
    const int*   ei      = (const int*)  d_in[1];
    const int*   batch   = (const int*)  d_in[2];
    const float* proj_w  = (const float*)d_in[3];
    const float* proj_b  = (const float*)d_in[4];
    const float* conv_w1 = (const float*)d_in[5];
    const float* conv_b1 = (const float*)d_in[6];
    const float* conv_w2 = (const float*)d_in[7];
    const float* conv_b2 = (const float*)d_in[8];
    const float* sh_w    = (const float*)d_in[9];
    const float* sh_b    = (const float*)d_in[10];
    const float* e_w     = (const float*)d_in[11];
    const float* e_b     = (const float*)d_in[12];
    const float* d_w     = (const float*)d_in[13];
    const float* d_b     = (const float*)d_in[14];
    float* out = (float*)d_out;

    float *h, *h2, *gsum;
    int *off, *cur, *csr, *bsum, *bpre, *gcnt;
    cudaGetSymbolAddress((void**)&h,    g_h);
    cudaGetSymbolAddress((void**)&h2,   g_h2);
    cudaGetSymbolAddress((void**)&off,  g_off);
    cudaGetSymbolAddress((void**)&cur,  g_cur);
    cudaGetSymbolAddress((void**)&csr,  g_csr);
    cudaGetSymbolAddress((void**)&bsum, g_bsum);
    cudaGetSymbolAddress((void**)&bpre, g_bpre);
    cudaGetSymbolAddress((void**)&gsum, g_gsum);
    cudaGetSymbolAddress((void**)&gcnt, g_gcnt);

    // input projection
    proj_kernel<<<NN, HH>>>(x, proj_w, proj_b, h);

    // CSR build (edges grouped by destination); deg accumulates in off[]
    zero_kernel<<<(GG * HH + 255) / 256, 256>>>(off, gsum, gcnt);
    hist_kernel<<<(EE + 255) / 256, 256>>>(ei, off);
    scan1_kernel<<<SCAN_NB, SCAN_B>>>(off, bsum);
    scan2_kernel<<<1, 256>>>(bsum, bpre);
    scan3_kernel<<<(NN + 256) / 256, 256>>>(off, bpre, cur);
    fill_kernel<<<(EE + 255) / 256, 256>>>(ei, cur, csr);

    // GIN layers (fused gather+MLP with f32x2 GEMM; ping-pong h <-> h2)
    const int mlp_blocks = (NN + 63) / 64;
    const float* src = h;
    float* dst = h2;
    for (int l = 0; l < LL; l++) {
        mlp_fused_kernel<<<mlp_blocks, 256>>>(src, dst, off, csr,
                                              conv_w1 + (size_t)l * HH * HH,
                                              conv_b1 + (size_t)l * HH,
                                              conv_w2 + (size_t)l * HH * HH,
                                              conv_b2 + (size_t)l * HH);
        const float* t = dst; dst = (float*)src; src = t;
    }
    const float* hf = src;   // final features

    pool_kernel<<<(NN * 32 + 255) / 256, 256>>>(hf, batch, gsum, gcnt);
    head_kernel<<<GG, HH>>>(gsum, gcnt, sh_w, sh_b, e_w, e_b, d_w, d_b, out);
}

// round 14
// speedup vs baseline: 1.0643x; 1.0076x over previous
#include <cuda_runtime.h>
#include <cuda_fp16.h>
#include <cuda_bf16.h>

#define NN 100000
#define EE 1600000
#define GG 2000
#define HH 128
#define LL 3
#define SCAN_B 512
#define SCAN_NB ((NN + SCAN_B - 1) / SCAN_B)   // 196
#define PITCH 132   // 4*PITCH % 32 == 16 -> row-groups 4 apart hit different banks

// Scratch (__device__ globals; no allocations allowed)
__device__ float  g_h  [NN * HH];
__device__ float  g_h2 [NN * HH];
__device__ __half g_hh [NN * HH];   // fp16 mirror (neighbor gather only)
__device__ __half g_hh2[NN * HH];
__device__ int    g_off[NN + 1];
__device__ int    g_cur[NN];
__device__ int    g_csr[EE];
__device__ int    g_bsum[256];
__device__ int    g_bpre[256];
__device__ float  g_gsum[GG * HH];
__device__ int    g_gcnt[GG];

// ---- packed f32x2 helpers (register-pure asm only; loads stay in C++) ----
#define FFMA2(acc, a, b) \
    asm("fma.rn.f32x2 %0, %1, %2, %0;" : "+l"(acc) : "l"(a), "l"(b))
#define PACK2F(out, lo, hi) \
    asm("mov.b64 %0, {%1, %2};" : "=l"(out) \
        : "r"(__float_as_uint(lo)), "r"(__float_as_uint(hi)))
#define UNPACK2(lo, hi, in) \
    asm("mov.b64 {%0, %1}, %2;" : "=r"(lo), "=r"(hi) : "l"(in))

// ---------------------------------------------------------------------------
__global__ void proj_kernel(const float* __restrict__ x,
                            const float* __restrict__ pw,
                            const float* __restrict__ pb,
                            float* __restrict__ h,
                            __half* __restrict__ hh) {
    int n = blockIdx.x;
    int j = threadIdx.x;
    const float* xr = x + (size_t)n * 4;
    float acc = pb[j];
    acc += xr[0] * pw[0 * HH + j];
    acc += xr[1] * pw[1 * HH + j];
    acc += xr[2] * pw[2 * HH + j];
    acc += xr[3] * pw[3 * HH + j];
    h [(size_t)n * HH + j] = acc;
    hh[(size_t)n * HH + j] = __float2half_rn(acc);
}

// ---------------------------------------------------------------------------
__global__ void zero_kernel(int* __restrict__ deg,
                            float* __restrict__ gsum, int* __restrict__ gcnt) {
    int i = blockIdx.x * blockDim.x + threadIdx.x;
    if (i <= NN) deg[i] = 0;
    if (i < GG * HH) gsum[i] = 0.f;
    if (i < GG) gcnt[i] = 0;
}

__global__ void hist_kernel(const int* __restrict__ ei, int* __restrict__ deg) {
    int e = blockIdx.x * blockDim.x + threadIdx.x;
    if (e < EE) atomicAdd(deg + __ldg(ei + EE + e), 1);
}

__global__ void scan1_kernel(int* __restrict__ off, int* __restrict__ bsum) {
    __shared__ int s[SCAN_B];
    int t = threadIdx.x;
    int i = blockIdx.x * SCAN_B + t;
    int v = (i < NN) ? off[i] : 0;
    s[t] = v;
    __syncthreads();
    for (int o = 1; o < SCAN_B; o <<= 1) {
        int x = (t >= o) ? s[t - o] : 0;
        __syncthreads();
        s[t] += x;
        __syncthreads();
    }
    if (i < NN) off[i] = s[t] - v;
    if (t == SCAN_B - 1) bsum[blockIdx.x] = s[t];
}

__global__ void scan2_kernel(const int* __restrict__ bsum, int* __restrict__ bpre) {
    __shared__ int s[256];
    int t = threadIdx.x;
    int v = (t < SCAN_NB) ? bsum[t] : 0;
    s[t] = v;
    __syncthreads();
    for (int o = 1; o < 256; o <<= 1) {
        int x = (t >= o) ? s[t - o] : 0;
        __syncthreads();
        s[t] += x;
        __syncthreads();
    }
    if (t < SCAN_NB) bpre[t] = s[t] - v;
}

__global__ void scan3_kernel(int* __restrict__ off, const int* __restrict__ bpre,
                             int* __restrict__ cur) {
    int i = blockIdx.x * blockDim.x + threadIdx.x;
    if (i < NN) {
        int o = off[i] + bpre[i / SCAN_B];
        off[i] = o;
        cur[i] = o;
    }
    if (i == NN) off[NN] = EE;
}

__global__ void fill_kernel(const int* __restrict__ ei,
                            int* __restrict__ cur, int* __restrict__ csr) {
    int e = blockIdx.x * blockDim.x + threadIdx.x;
    if (e < EE) {
        int s = __ldg(ei + e);
        int d = __ldg(ei + EE + e);
        int p = atomicAdd(cur + d, 1);
        csr[p] = s;
    }
}

// ---------------------------------------------------------------------------
// Fused: gather (m = h_fp32 + sum_nbr h_fp16) into smem tile, then
//        h_out = relu( relu(m @ W1 + b1) @ W2 + b2 )  via packed f32x2 FMA.
// Neighbor rows read from the fp16 mirror (8 B/lane) -> half the L2 bytes.
// Epilogue writes both fp32 h_out and fp16 mirror for the next layer.
__global__ void __launch_bounds__(256, 4) mlp_fused_kernel(
    const float* __restrict__ in, const __half* __restrict__ inh,
    float* __restrict__ out, __half* __restrict__ outh,
    const int* __restrict__ off, const int* __restrict__ csr,
    const float* __restrict__ W1, const float* __restrict__ B1,
    const float* __restrict__ W2, const float* __restrict__ B2) {
    __shared__ float sMT[64 * PITCH];
    __shared__ float sW[16 * HH];

    int tid  = threadIdx.x;
    int lane = tid & 31;
    int wrp  = tid >> 5;
    int row0 = blockIdx.x * 64;
    const float4* in4  = (const float4*)in;
    const uint2*  inh2 = (const uint2*)inh;   // 4 halfs per lane-chunk

    // ---- gather phase: 4 pairs of rows, interleaved edge loops ----
#pragma unroll
    for (int jj = 0; jj < 4; jj++) {
        int r0 = wrp * 8 + jj * 2;
        int n0 = row0 + r0;
        int n1 = n0 + 1;
        float4 a0 = make_float4(0.f, 0.f, 0.f, 0.f);
        float4 a1 = make_float4(0.f, 0.f, 0.f, 0.f);
        int d0 = 0, d1 = 0, s0 = 0, s1 = 0;
        if (n0 < NN) {
            a0 = __ldg(in4 + (size_t)n0 * 32 + lane);
            s0 = __ldg(off + n0);
            d0 = __ldg(off + n0 + 1) - s0;
        }
        if (n1 < NN) {
            a1 = __ldg(in4 + (size_t)n1 * 32 + lane);
            s1 = __ldg(off + n1);
            d1 = __ldg(off + n1 + 1) - s1;
        }
        int dmax = d0 > d1 ? d0 : d1;
#pragma unroll 4
        for (int e = 0; e < dmax; e++) {
            if (e < d0) {            // warp-uniform branch
                int s = __ldg(csr + s0 + e);
                uint2 p = __ldg(inh2 + (size_t)s * 32 + lane);
                float2 f01 = __half22float2(*(__half2*)&p.x);
                float2 f23 = __half22float2(*(__half2*)&p.y);
                a0.x += f01.x; a0.y += f01.y; a0.z += f23.x; a0.w += f23.y;
            }
            if (e < d1) {            // warp-uniform branch
                int s = __ldg(csr + s1 + e);
                uint2 p = __ldg(inh2 + (size_t)s * 32 + lane);
                float2 f01 = __half22float2(*(__half2*)&p.x);
                float2 f23 = __half22float2(*(__half2*)&p.y);
                a1.x += f01.x; a1.y += f01.y; a1.z += f23.x; a1.w += f23.y;
            }
        }
        *(float4*)(sMT + r0 * PITCH + lane * 4)       = a0;
        *(float4*)(sMT + (r0 + 1) * PITCH + lane * 4) = a1;
    }

    int rb = tid >> 4;            // 0..15  -> rows rb*4 .. rb*4+3
    int cg = (tid & 15) * 8;      // 0..120 step 8

    unsigned long long acc2[4][4];
#pragma unroll
    for (int i = 0; i < 4; i++)
#pragma unroll
        for (int j = 0; j < 4; j++) acc2[i][j] = 0ULL;

    // ---- GEMM 1: t = m @ W1 ----
    for (int kc = 0; kc < HH; kc += 16) {
        __syncthreads();
        for (int i = tid; i < 16 * 32; i += 256)
            ((float4*)sW)[i] = ((const float4*)(W1 + (size_t)kc * HH))[i];
        __syncthreads();
#pragma unroll
        for (int k = 0; k < 16; k++) {
            float4 w0 = *(const float4*)(sW + k * HH + cg);
            float4 w1 = *(const float4*)(sW + k * HH + cg + 4);
            unsigned long long w01, w23, w45, w67;
            PACK2F(w01, w0.x, w0.y);
            PACK2F(w23, w0.z, w0.w);
            PACK2F(w45, w1.x, w1.y);
            PACK2F(w67, w1.z, w1.w);
#pragma unroll
            for (int i = 0; i < 4; i++) {
                float m = sMT[(rb * 4 + i) * PITCH + kc + k];
                unsigned long long m2;
                PACK2F(m2, m, m);
                FFMA2(acc2[i][0], m2, w01);
                FFMA2(acc2[i][1], m2, w23);
                FFMA2(acc2[i][2], m2, w45);
                FFMA2(acc2[i][3], m2, w67);
            }
        }
    }
    __syncthreads();

    // t = relu(acc + b1) -> sMT
    {
#pragma unroll
        for (int i = 0; i < 4; i++) {
            int r = rb * 4 + i;
            float v[8];
#pragma unroll
            for (int j = 0; j < 4; j++) {
                unsigned int lo, hi;
                UNPACK2(lo, hi, acc2[i][j]);
                v[2 * j]     = __uint_as_float(lo);
                v[2 * j + 1] = __uint_as_float(hi);
                acc2[i][j] = 0ULL;
            }
            float4 t0, t1;
            t0.x = fmaxf(v[0] + B1[cg],     0.f);
            t0.y = fmaxf(v[1] + B1[cg + 1], 0.f);
            t0.z = fmaxf(v[2] + B1[cg + 2], 0.f);
            t0.w = fmaxf(v[3] + B1[cg + 3], 0.f);
            t1.x = fmaxf(v[4] + B1[cg + 4], 0.f);
            t1.y = fmaxf(v[5] + B1[cg + 5], 0.f);
            t1.z = fmaxf(v[6] + B1[cg + 6], 0.f);
            t1.w = fmaxf(v[7] + B1[cg + 7], 0.f);
            *(float4*)(sMT + r * PITCH + cg)     = t0;
            *(float4*)(sMT + r * PITCH + cg + 4) = t1;
        }
    }

    // ---- GEMM 2: o = t @ W2 ----
    for (int kc = 0; kc < HH; kc += 16) {
        __syncthreads();
        for (int i = tid; i < 16 * 32; i += 256)
            ((float4*)sW)[i] = ((const float4*)(W2 + (size_t)kc * HH))[i];
        __syncthreads();
#pragma unroll
        for (int k = 0; k < 16; k++) {
            float4 w0 = *(const float4*)(sW + k * HH + cg);
            float4 w1 = *(const float4*)(sW + k * HH + cg + 4);
            unsigned long long w01, w23, w45, w67;
            PACK2F(w01, w0.x, w0.y);
            PACK2F(w23, w0.z, w0.w);
            PACK2F(w45, w1.x, w1.y);
            PACK2F(w67, w1.z, w1.w);
#pragma unroll
            for (int i = 0; i < 4; i++) {
                float t = sMT[(rb * 4 + i) * PITCH + kc + k];
                unsigned long long t2;
                PACK2F(t2, t, t);
                FFMA2(acc2[i][0], t2, w01);
                FFMA2(acc2[i][1], t2, w23);
                FFMA2(acc2[i][2], t2, w45);
                FFMA2(acc2[i][3], t2, w67);
            }
        }
    }

    // h_out = relu(acc + b2)  (write fp32 + fp16 mirror)
    {
#pragma unroll
        for (int i = 0; i < 4; i++) {
            int n = row0 + rb * 4 + i;
            if (n < NN) {
                float v[8];
#pragma unroll
                for (int j = 0; j < 4; j++) {
                    unsigned int lo, hi;
                    UNPACK2(lo, hi, acc2[i][j]);
                    v[2 * j]     = __uint_as_float(lo);
                    v[2 * j + 1] = __uint_as_float(hi);
                }
                float4 o0, o1;
                o0.x = fmaxf(v[0] + B2[cg],     0.f);
                o0.y = fmaxf(v[1] + B2[cg + 1], 0.f);
                o0.z = fmaxf(v[2] + B2[cg + 2], 0.f);
                o0.w = fmaxf(v[3] + B2[cg + 3], 0.f);
                o1.x = fmaxf(v[4] + B2[cg + 4], 0.f);
                o1.y = fmaxf(v[5] + B2[cg + 5], 0.f);
                o1.z = fmaxf(v[6] + B2[cg + 6], 0.f);
                o1.w = fmaxf(v[7] + B2[cg + 7], 0.f);
                *(float4*)(out + (size_t)n * HH + cg)     = o0;
                *(float4*)(out + (size_t)n * HH + cg + 4) = o1;
                __half2 q0 = __floats2half2_rn(o0.x, o0.y);
                __half2 q1 = __floats2half2_rn(o0.z, o0.w);
                __half2 q2 = __floats2half2_rn(o1.x, o1.y);
                __half2 q3 = __floats2half2_rn(o1.z, o1.w);
                uint4 q;
                q.x = *(unsigned int*)&q0;
                q.y = *(unsigned int*)&q1;
                q.z = *(unsigned int*)&q2;
                q.w = *(unsigned int*)&q3;
                *(uint4*)(outh + (size_t)n * HH + cg) = q;
            }
        }
    }
}

// ---------------------------------------------------------------------------
__global__ void pool_kernel(const float* __restrict__ h, const int* __restrict__ batch,
                            float* __restrict__ gsum, int* __restrict__ gcnt) {
    int n = (blockIdx.x * blockDim.x + threadIdx.x) >> 5;
    if (n >= NN) return;
    int lane = threadIdx.x & 31;
    int b = __ldg(batch + n);
    float4 v = ((const float4*)(h + (size_t)n * HH))[lane];
    float* dst = gsum + (size_t)b * HH + lane * 4;
    atomicAdd(dst + 0, v.x);
    atomicAdd(dst + 1, v.y);
    atomicAdd(dst + 2, v.z);
    atomicAdd(dst + 3, v.w);
    if (lane == 0) atomicAdd(gcnt + b, 1);
}

// ---------------------------------------------------------------------------
__global__ void head_kernel(const float* __restrict__ gsum, const int* __restrict__ gcnt,
                            const float* __restrict__ Ws, const float* __restrict__ Bs,
                            const float* __restrict__ ew, const float* __restrict__ eb,
                            const float* __restrict__ dw, const float* __restrict__ db,
                            float* __restrict__ out) {
    int g = blockIdx.x;
    int j = threadIdx.x;
    __shared__ float sg[HH];
    __shared__ float re[HH];
    __shared__ float rd[HH];

    float cnt = fmaxf((float)gcnt[g], 1.f);
    sg[j] = gsum[(size_t)g * HH + j] / cnt;
    __syncthreads();

    float a = Bs[j];
#pragma unroll 8
    for (int k = 0; k < HH; k++) a += sg[k] * Ws[k * HH + j];
    a = fmaxf(a, 0.f);

    re[j] = a * ew[j];
    rd[j] = a * dw[j];
    __syncthreads();
    for (int s = 64; s > 0; s >>= 1) {
        if (j < s) { re[j] += re[j + s]; rd[j] += rd[j + s]; }
        __syncthreads();
    }
    if (j == 0) {
        out[g]      = re[0] + eb[0];
        out[GG + g] = rd[0] + db[0];
    }
}

// ---------------------------------------------------------------------------
extern "C" void kernel_launch(void* const* d_in, const int* in_sizes, int n_in,
                              void* d_out, int out_size) {
    const float* x       = (const float*)d_in[0];
    const int*   ei      = (const int*)  d_in[1];
    const int*   batch   = (const int*)  d_in[2];
    const float* proj_w  = (const float*)d_in[3];
    const float* proj_b  = (const float*)d_in[4];
    const float* conv_w1 = (const float*)d_in[5];
    const float* conv_b1 = (const float*)d_in[6];
    const float* conv_w2 = (const float*)d_in[7];
    const float* conv_b2 = (const float*)d_in[8];
    const float* sh_w    = (const float*)d_in[9];
    const float* sh_b    = (const float*)d_in[10];
    const float* e_w     = (const float*)d_in[11];
    const float* e_b     = (const float*)d_in[12];
    const float* d_w     = (const float*)d_in[13];
    const float* d_b     = (const float*)d_in[14];
    float* out = (float*)d_out;

    float *h, *h2, *gsum;
    __half *hh, *hh2;
    int *off, *cur, *csr, *bsum, *bpre, *gcnt;
    cudaGetSymbolAddress((void**)&h,    g_h);
    cudaGetSymbolAddress((void**)&h2,   g_h2);
    cudaGetSymbolAddress((void**)&hh,   g_hh);
    cudaGetSymbolAddress((void**)&hh2,  g_hh2);
    cudaGetSymbolAddress((void**)&off,  g_off);
    cudaGetSymbolAddress((void**)&cur,  g_cur);
    cudaGetSymbolAddress((void**)&csr,  g_csr);
    cudaGetSymbolAddress((void**)&bsum, g_bsum);
    cudaGetSymbolAddress((void**)&bpre, g_bpre);
    cudaGetSymbolAddress((void**)&gsum, g_gsum);
    cudaGetSymbolAddress((void**)&gcnt, g_gcnt);

    // input projection (fp32 + fp16 mirror)
    proj_kernel<<<NN, HH>>>(x, proj_w, proj_b, h, hh);

    // CSR build (edges grouped by destination); deg accumulates in off[]
    zero_kernel<<<(GG * HH + 255) / 256, 256>>>(off, gsum, gcnt);
    hist_kernel<<<(EE + 255) / 256, 256>>>(ei, off);
    scan1_kernel<<<SCAN_NB, SCAN_B>>>(off, bsum);
    scan2_kernel<<<1, 256>>>(bsum, bpre);
    scan3_kernel<<<(NN + 256) / 256, 256>>>(off, bpre, cur);
    fill_kernel<<<(EE + 255) / 256, 256>>>(ei, cur, csr);

    // GIN layers (fused gather+MLP; ping-pong both fp32 and fp16 buffers)
    const int mlp_blocks = (NN + 63) / 64;
    const float*  src  = h;
    const __half* srch = hh;
    float*  dst  = h2;
    __half* dsth = hh2;
    for (int l = 0; l < LL; l++) {
        mlp_fused_kernel<<<mlp_blocks, 256>>>(src, srch, dst, dsth, off, csr,
                                              conv_w1 + (size_t)l * HH * HH,
                                              conv_b1 + (size_t)l * HH,
                                              conv_w2 + (size_t)l * HH * HH,
                                              conv_b2 + (size_t)l * HH);
        const float*  t  = dst;  dst  = (float*)src;   src  = t;
        const __half* th = dsth; dsth = (__half*)srch; srch = th;
    }
    const float* hf = src;   // final fp32 features

    pool_kernel<<<(NN * 32 + 255) / 256, 256>>>(hf, batch, gsum, gcnt);
    head_kernel<<<GG, HH>>>(gsum, gcnt, sh_w, sh_b, e_w, e_b, d_w, d_b, out);
}

// round 17
// speedup vs baseline: 1.1102x; 1.0431x over previous
#include <cuda_runtime.h>
#include <cuda_fp16.h>
#include <cuda_bf16.h>

#define NN 100000
#define EE 1600000
#define GG 2000
#define HH 128
#define LL 3
#define SCAN_B 512
#define SCAN_NB ((NN + SCAN_B - 1) / SCAN_B)   // 196
#define PITCH 132   // 4*PITCH % 32 == 16 -> row-groups 4 apart hit different banks

// Scratch (__device__ globals; no allocations allowed)
__device__ float  g_h  [NN * HH];
__device__ float  g_h2 [NN * HH];
__device__ __half g_hh [NN * HH];   // fp16 mirror (gather reads)
__device__ __half g_hh2[NN * HH];
__device__ int    g_off[NN + 1];
__device__ int    g_cur[NN];
__device__ int    g_csr[EE];
__device__ int    g_bsum[256];
__device__ int    g_bpre[256];
__device__ float  g_gsum[GG * HH];
__device__ int    g_gcnt[GG];

// ---- packed f32x2 helpers (register-pure asm only; loads stay in C++) ----
#define FFMA2(acc, a, b) \
    asm("fma.rn.f32x2 %0, %1, %2, %0;" : "+l"(acc) : "l"(a), "l"(b))
#define PACK2F(out, lo, hi) \
    asm("mov.b64 %0, {%1, %2};" : "=l"(out) \
        : "r"(__float_as_uint(lo)), "r"(__float_as_uint(hi)))
#define UNPACK2(lo, hi, in) \
    asm("mov.b64 {%0, %1}, %2;" : "=r"(lo), "=r"(hi) : "l"(in))

__device__ __forceinline__ void red_add_v4(float* p, float4 v) {
    asm volatile("red.global.add.v4.f32 [%0], {%1, %2, %3, %4};"
                 :: "l"(p), "f"(v.x), "f"(v.y), "f"(v.z), "f"(v.w)
                 : "memory");
}

// ---------------------------------------------------------------------------
__global__ void proj_kernel(const float* __restrict__ x,
                            const float* __restrict__ pw,
                            const float* __restrict__ pb,
                            float* __restrict__ h,
                            __half* __restrict__ hh) {
    int n = blockIdx.x;
    int j = threadIdx.x;
    const float* xr = x + (size_t)n * 4;
    float acc = pb[j];
    acc += xr[0] * pw[0 * HH + j];
    acc += xr[1] * pw[1 * HH + j];
    acc += xr[2] * pw[2 * HH + j];
    acc += xr[3] * pw[3 * HH + j];
    h [(size_t)n * HH + j] = acc;
    hh[(size_t)n * HH + j] = __float2half_rn(acc);
}

// ---------------------------------------------------------------------------
__global__ void zero_kernel(int* __restrict__ deg,
                            float* __restrict__ gsum, int* __restrict__ gcnt) {
    int i = blockIdx.x * blockDim.x + threadIdx.x;
    if (i <= NN) deg[i] = 0;
    if (i < GG * HH) gsum[i] = 0.f;
    if (i < GG) gcnt[i] = 0;
}

__global__ void hist_kernel(const int* __restrict__ ei, int* __restrict__ deg) {
    int e = blockIdx.x * blockDim.x + threadIdx.x;
    if (e < EE) atomicAdd(deg + __ldg(ei + EE + e), 1);
}

__global__ void scan1_kernel(int* __restrict__ off, int* __restrict__ bsum) {
    __shared__ int s[SCAN_B];
    int t = threadIdx.x;
    int i = blockIdx.x * SCAN_B + t;
    int v = (i < NN) ? off[i] : 0;
    s[t] = v;
    __syncthreads();
    for (int o = 1; o < SCAN_B; o <<= 1) {
        int x = (t >= o) ? s[t - o] : 0;
        __syncthreads();
        s[t] += x;
        __syncthreads();
    }
    if (i < NN) off[i] = s[t] - v;
    if (t == SCAN_B - 1) bsum[blockIdx.x] = s[t];
}

__global__ void scan2_kernel(const int* __restrict__ bsum, int* __restrict__ bpre) {
    __shared__ int s[256];
    int t = threadIdx.x;
    int v = (t < SCAN_NB) ? bsum[t] : 0;
    s[t] = v;
    __syncthreads();
    for (int o = 1; o < 256; o <<= 1) {
        int x = (t >= o) ? s[t - o] : 0;
        __syncthreads();
        s[t] += x;
        __syncthreads();
    }
    if (t < SCAN_NB) bpre[t] = s[t] - v;
}

__global__ void scan3_kernel(int* __restrict__ off, const int* __restrict__ bpre,
                             int* __restrict__ cur) {
    int i = blockIdx.x * blockDim.x + threadIdx.x;
    if (i < NN) {
        int o = off[i] + bpre[i / SCAN_B];
        off[i] = o;
        cur[i] = o;
    }
    if (i == NN) off[NN] = EE;
}

__global__ void fill_kernel(const int* __restrict__ ei,
                            int* __restrict__ cur, int* __restrict__ csr) {
    int e = blockIdx.x * blockDim.x + threadIdx.x;
    if (e < EE) {
        int s = __ldg(ei + e);
        int d = __ldg(ei + EE + e);
        int p = atomicAdd(cur + d, 1);
        csr[p] = s;
    }
}

// ---------------------------------------------------------------------------
// Fused: gather (m = self + sum_nbr, all rows from fp16 mirror) into smem,
// then h_out = relu( relu(m @ W1 + b1) @ W2 + b2 ) via packed f32x2 FMA.
// Epilogue writes fp32 h_out + fp16 mirror for the next layer.
__global__ void __launch_bounds__(256, 4) mlp_fused_kernel(
    const __half* __restrict__ inh,
    float* __restrict__ out, __half* __restrict__ outh,
    const int* __restrict__ off, const int* __restrict__ csr,
    const float* __restrict__ W1, const float* __restrict__ B1,
    const float* __restrict__ W2, const float* __restrict__ B2) {
    __shared__ float sMT[64 * PITCH];
    __shared__ float sW[16 * HH];

    int tid  = threadIdx.x;
    int lane = tid & 31;
    int wrp  = tid >> 5;
    int row0 = blockIdx.x * 64;
    const uint2* inh2 = (const uint2*)inh;

    // ---- gather phase: 4 pairs of rows, interleaved edge loops ----
#pragma unroll
    for (int jj = 0; jj < 4; jj++) {
        int r0 = wrp * 8 + jj * 2;
        int n0 = row0 + r0;
        int n1 = n0 + 1;
        float4 a0 = make_float4(0.f, 0.f, 0.f, 0.f);
        float4 a1 = make_float4(0.f, 0.f, 0.f, 0.f);
        int d0 = 0, d1 = 0, s0 = 0, s1 = 0;
        if (n0 < NN) {
            uint2 p = __ldg(inh2 + (size_t)n0 * 32 + lane);
            float2 f01 = __half22float2(*(__half2*)&p.x);
            float2 f23 = __half22float2(*(__half2*)&p.y);
            a0 = make_float4(f01.x, f01.y, f23.x, f23.y);
            s0 = __ldg(off + n0);
            d0 = __ldg(off + n0 + 1) - s0;
        }
        if (n1 < NN) {
            uint2 p = __ldg(inh2 + (size_t)n1 * 32 + lane);
            float2 f01 = __half22float2(*(__half2*)&p.x);
            float2 f23 = __half22float2(*(__half2*)&p.y);
            a1 = make_float4(f01.x, f01.y, f23.x, f23.y);
            s1 = __ldg(off + n1);
            d1 = __ldg(off + n1 + 1) - s1;
        }
        int dmax = d0 > d1 ? d0 : d1;
#pragma unroll 4
        for (int e = 0; e < dmax; e++) {
            if (e < d0) {            // warp-uniform branch
                int s = __ldg(csr + s0 + e);
                uint2 p = __ldg(inh2 + (size_t)s * 32 + lane);
                float2 f01 = __half22float2(*(__half2*)&p.x);
                float2 f23 = __half22float2(*(__half2*)&p.y);
                a0.x += f01.x; a0.y += f01.y; a0.z += f23.x; a0.w += f23.y;
            }
            if (e < d1) {            // warp-uniform branch
                int s = __ldg(csr + s1 + e);
                uint2 p = __ldg(inh2 + (size_t)s * 32 + lane);
                float2 f01 = __half22float2(*(__half2*)&p.x);
                float2 f23 = __half22float2(*(__half2*)&p.y);
                a1.x += f01.x; a1.y += f01.y; a1.z += f23.x; a1.w += f23.y;
            }
        }
        *(float4*)(sMT + r0 * PITCH + lane * 4)       = a0;
        *(float4*)(sMT + (r0 + 1) * PITCH + lane * 4) = a1;
    }

    int rb = tid >> 4;            // 0..15  -> rows rb*4 .. rb*4+3
    int cg = (tid & 15) * 8;      // 0..120 step 8

    unsigned long long acc2[4][4];
#pragma unroll
    for (int i = 0; i < 4; i++)
#pragma unroll
        for (int j = 0; j < 4; j++) acc2[i][j] = 0ULL;

    // ---- GEMM 1: t = m @ W1 ----
    for (int kc = 0; kc < HH; kc += 16) {
        __syncthreads();
        for (int i = tid; i < 16 * 32; i += 256)
            ((float4*)sW)[i] = ((const float4*)(W1 + (size_t)kc * HH))[i];
        __syncthreads();
#pragma unroll
        for (int k = 0; k < 16; k++) {
            float4 w0 = *(const float4*)(sW + k * HH + cg);
            float4 w1 = *(const float4*)(sW + k * HH + cg + 4);
            unsigned long long w01, w23, w45, w67;
            PACK2F(w01, w0.x, w0.y);
            PACK2F(w23, w0.z, w0.w);
            PACK2F(w45, w1.x, w1.y);
            PACK2F(w67, w1.z, w1.w);
#pragma unroll
            for (int i = 0; i < 4; i++) {
                float m = sMT[(rb * 4 + i) * PITCH + kc + k];
                unsigned long long m2;
                PACK2F(m2, m, m);
                FFMA2(acc2[i][0], m2, w01);
                FFMA2(acc2[i][1], m2, w23);
                FFMA2(acc2[i][2], m2, w45);
                FFMA2(acc2[i][3], m2, w67);
            }
        }
    }
    __syncthreads();

    // t = relu(acc + b1) -> sMT
    {
#pragma unroll
        for (int i = 0; i < 4; i++) {
            int r = rb * 4 + i;
            float v[8];
#pragma unroll
            for (int j = 0; j < 4; j++) {
                unsigned int lo, hi;
                UNPACK2(lo, hi, acc2[i][j]);
                v[2 * j]     = __uint_as_float(lo);
                v[2 * j + 1] = __uint_as_float(hi);
                acc2[i][j] = 0ULL;
            }
            float4 t0, t1;
            t0.x = fmaxf(v[0] + B1[cg],     0.f);
            t0.y = fmaxf(v[1] + B1[cg + 1], 0.f);
            t0.z = fmaxf(v[2] + B1[cg + 2], 0.f);
            t0.w = fmaxf(v[3] + B1[cg + 3], 0.f);
            t1.x = fmaxf(v[4] + B1[cg + 4], 0.f);
            t1.y = fmaxf(v[5] + B1[cg + 5], 0.f);
            t1.z = fmaxf(v[6] + B1[cg + 6], 0.f);
            t1.w = fmaxf(v[7] + B1[cg + 7], 0.f);
            *(float4*)(sMT + r * PITCH + cg)     = t0;
            *(float4*)(sMT + r * PITCH + cg + 4) = t1;
        }
    }

    // ---- GEMM 2: o = t @ W2 ----
    for (int kc = 0; kc < HH; kc += 16) {
        __syncthreads();
        for (int i = tid; i < 16 * 32; i += 256)
            ((float4*)sW)[i] = ((const float4*)(W2 + (size_t)kc * HH))[i];
        __syncthreads();
#pragma unroll
        for (int k = 0; k < 16; k++) {
            float4 w0 = *(const float4*)(sW + k * HH + cg);
            float4 w1 = *(const float4*)(sW + k * HH + cg + 4);
            unsigned long long w01, w23, w45, w67;
            PACK2F(w01, w0.x, w0.y);
            PACK2F(w23, w0.z, w0.w);
            PACK2F(w45, w1.x, w1.y);
            PACK2F(w67, w1.z, w1.w);
#pragma unroll
            for (int i = 0; i < 4; i++) {
                float t = sMT[(rb * 4 + i) * PITCH + kc + k];
                unsigned long long t2;
                PACK2F(t2, t, t);
                FFMA2(acc2[i][0], t2, w01);
                FFMA2(acc2[i][1], t2, w23);
                FFMA2(acc2[i][2], t2, w45);
                FFMA2(acc2[i][3], t2, w67);
            }
        }
    }

    // h_out = relu(acc + b2)  (write fp32 + fp16 mirror)
    {
#pragma unroll
        for (int i = 0; i < 4; i++) {
            int n = row0 + rb * 4 + i;
            if (n < NN) {
                float v[8];
#pragma unroll
                for (int j = 0; j < 4; j++) {
                    unsigned int lo, hi;
                    UNPACK2(lo, hi, acc2[i][j]);
                    v[2 * j]     = __uint_as_float(lo);
                    v[2 * j + 1] = __uint_as_float(hi);
                }
                float4 o0, o1;
                o0.x = fmaxf(v[0] + B2[cg],     0.f);
                o0.y = fmaxf(v[1] + B2[cg + 1], 0.f);
                o0.z = fmaxf(v[2] + B2[cg + 2], 0.f);
                o0.w = fmaxf(v[3] + B2[cg + 3], 0.f);
                o1.x = fmaxf(v[4] + B2[cg + 4], 0.f);
                o1.y = fmaxf(v[5] + B2[cg + 5], 0.f);
                o1.z = fmaxf(v[6] + B2[cg + 6], 0.f);
                o1.w = fmaxf(v[7] + B2[cg + 7], 0.f);
                *(float4*)(out + (size_t)n * HH + cg)     = o0;
                *(float4*)(out + (size_t)n * HH + cg + 4) = o1;
                __half2 q0 = __floats2half2_rn(o0.x, o0.y);
                __half2 q1 = __floats2half2_rn(o0.z, o0.w);
                __half2 q2 = __floats2half2_rn(o1.x, o1.y);
                __half2 q3 = __floats2half2_rn(o1.z, o1.w);
                uint4 q;
                q.x = *(unsigned int*)&q0;
                q.y = *(unsigned int*)&q1;
                q.z = *(unsigned int*)&q2;
                q.w = *(unsigned int*)&q3;
                *(uint4*)(outh + (size_t)n * HH + cg) = q;
            }
        }
    }
}

// ---------------------------------------------------------------------------
__global__ void pool_kernel(const float* __restrict__ h, const int* __restrict__ batch,
                            float* __restrict__ gsum, int* __restrict__ gcnt) {
    int n = (blockIdx.x * blockDim.x + threadIdx.x) >> 5;
    if (n >= NN) return;
    int lane = threadIdx.x & 31;
    int b = __ldg(batch + n);
    float4 v = ((const float4*)(h + (size_t)n * HH))[lane];
    red_add_v4(gsum + (size_t)b * HH + lane * 4, v);
    if (lane == 0) atomicAdd(gcnt + b, 1);
}

// ---------------------------------------------------------------------------
__global__ void head_kernel(const float* __restrict__ gsum, const int* __restrict__ gcnt,
                            const float* __restrict__ Ws, const float* __restrict__ Bs,
                            const float* __restrict__ ew, const float* __restrict__ eb,
                            const float* __restrict__ dw, const float* __restrict__ db,
                            float* __restrict__ out) {
    int g = blockIdx.x;
    int j = threadIdx.x;
    __shared__ float sg[HH];
    __shared__ float re[HH];
    __shared__ float rd[HH];

    float cnt = fmaxf((float)gcnt[g], 1.f);
    sg[j] = gsum[(size_t)g * HH + j] / cnt;
    __syncthreads();

    float a = Bs[j];
#pragma unroll 8
    for (int k = 0; k < HH; k++) a += sg[k] * Ws[k * HH + j];
    a = fmaxf(a, 0.f);

    re[j] = a * ew[j];
    rd[j] = a * dw[j];
    __syncthreads();
    for (int s = 64; s > 0; s >>= 1) {
        if (j < s) { re[j] += re[j + s]; rd[j] += rd[j + s]; }
        __syncthreads();
    }
    if (j == 0) {
        out[g]      = re[0] + eb[0];
        out[GG + g] = rd[0] + db[0];
    }
}

// ---------------------------------------------------------------------------
extern "C" void kernel_launch(void* const* d_in, const int* in_sizes, int n_in,
                              void* d_out, int out_size) {
    const float* x       = (const float*)d_in[0];
    const int*   ei      = (const int*)  d_in[1];
    const int*   batch   = (const int*)  d_in[2];
    const float* proj_w  = (const float*)d_in[3];
    const float* proj_b  = (const float*)d_in[4];
    const float* conv_w1 = (const float*)d_in[5];
    const float* conv_b1 = (const float*)d_in[6];
    const float* conv_w2 = (const float*)d_in[7];
    const float* conv_b2 = (const float*)d_in[8];
    const float* sh_w    = (const float*)d_in[9];
    const float* sh_b    = (const float*)d_in[10];
    const float* e_w     = (const float*)d_in[11];
    const float* e_b     = (const float*)d_in[12];
    const float* d_w     = (const float*)d_in[13];
    const float* d_b     = (const float*)d_in[14];
    float* out = (float*)d_out;

    float *h, *h2, *gsum;
    __half *hh, *hh2;
    int *off, *cur, *csr, *bsum, *bpre, *gcnt;
    cudaGetSymbolAddress((void**)&h,    g_h);
    cudaGetSymbolAddress((void**)&h2,   g_h2);
    cudaGetSymbolAddress((void**)&hh,   g_hh);
    cudaGetSymbolAddress((void**)&hh2,  g_hh2);
    cudaGetSymbolAddress((void**)&off,  g_off);
    cudaGetSymbolAddress((void**)&cur,  g_cur);
    cudaGetSymbolAddress((void**)&csr,  g_csr);
    cudaGetSymbolAddress((void**)&bsum, g_bsum);
    cudaGetSymbolAddress((void**)&bpre, g_bpre);
    cudaGetSymbolAddress((void**)&gsum, g_gsum);
    cudaGetSymbolAddress((void**)&gcnt, g_gcnt);

    // input projection (fp32 + fp16 mirror)
    proj_kernel<<<NN, HH>>>(x, proj_w, proj_b, h, hh);

    // CSR build (edges grouped by destination); deg accumulates in off[]
    zero_kernel<<<(GG * HH + 255) / 256, 256>>>(off, gsum, gcnt);
    hist_kernel<<<(EE + 255) / 256, 256>>>(ei, off);
    scan1_kernel<<<SCAN_NB, SCAN_B>>>(off, bsum);
    scan2_kernel<<<1, 256>>>(bsum, bpre);
    scan3_kernel<<<(NN + 256) / 256, 256>>>(off, bpre, cur);
    fill_kernel<<<(EE + 255) / 256, 256>>>(ei, cur, csr);

    // GIN layers (fused gather+MLP; ping-pong fp32 and fp16 buffers)
    const int mlp_blocks = (NN + 63) / 64;
    const __half* srch = hh;
    float*  dst  = h2;
    __half* dsth = hh2;
    for (int l = 0; l < LL; l++) {
        mlp_fused_kernel<<<mlp_blocks, 256>>>(srch, dst, dsth, off, csr,
                                              conv_w1 + (size_t)l * HH * HH,
                                              conv_b1 + (size_t)l * HH,
                                              conv_w2 + (size_t)l * HH * HH,
                                              conv_b2 + (size_t)l * HH);
        srch = dsth;
        dst  = (dst  == h2) ? h  : h2;
        dsth = (dsth == hh2) ? hh : hh2;
    }
    // after 3 iterations: L1 wrote h2/hh2, L2 wrote h/hh, L3 wrote h2/hh2
    const float* hf = h2;

    pool_kernel<<<(NN * 32 + 255) / 256, 256>>>(hf, batch, gsum, gcnt);
    head_kernel<<<GG, HH>>>(gsum, gcnt, sh_w, sh_b, e_w, e_b, d_w, d_b, out);
}